// round 14
// baseline (speedup 1.0000x reference)
#include <cuda_runtime.h>
#include <cuda_bf16.h>
#include <cstdint>
#include <math.h>

#define NNODES 65536   // nodes per branch (B*S)
#define NB     8192    // graph blocks
#define SS     8       // nodes per block
#define EPB    64      // edges per block
#define DIN    512
#define DOUT   256

// ---- scratch (static device globals; no allocation allowed) ----
__device__ float g_pos_pool[NB * DOUT];
__device__ float g_neg_pool[NB * DOUT];
__device__ float g_anchor[NB * DOUT];
__device__ __nv_bfloat16 g_wt_hi[DOUT * DIN];   // W_gcn^T split-hi [256][512]
__device__ __nv_bfloat16 g_wt_lo[DOUT * DIN];   // W_gcn^T split-lo
__device__ __nv_bfloat16 g_wb_hi[DOUT * DOUT];  // W_bil split-hi [256][256]
__device__ __nv_bfloat16 g_wb_lo[DOUT * DOUT];  // W_bil split-lo

// ======================= helpers =======================
__device__ __forceinline__ uint32_t smem_u32(const void* p) {
    uint32_t a;
    asm("{ .reg .u64 t; cvta.to.shared.u64 t, %1; cvt.u32.u64 %0, t; }"
        : "=r"(a) : "l"(p));
    return a;
}

#define LDSM_X4(r0, r1, r2, r3, addr) \
    asm volatile("ldmatrix.sync.aligned.m8n8.x4.shared.b16 {%0,%1,%2,%3}, [%4];" \
        : "=r"(r0), "=r"(r1), "=r"(r2), "=r"(r3) : "r"(addr))

#define MMA16816(d, a, b0, b1) \
    asm volatile("mma.sync.aligned.m16n8k16.row.col.f32.bf16.bf16.f32 " \
        "{%0,%1,%2,%3}, {%4,%5,%6,%7}, {%8,%9}, {%0,%1,%2,%3};" \
        : "+f"((d)[0]), "+f"((d)[1]), "+f"((d)[2]), "+f"((d)[3]) \
        : "r"((a)[0]), "r"((a)[1]), "r"((a)[2]), "r"((a)[3]), "r"(b0), "r"(b1))

#define CP_ASYNC16(dst, src) \
    asm volatile("cp.async.cg.shared.global [%0], [%1], 16;" \
                 :: "r"(dst), "l"(src) : "memory")
#define CP_COMMIT() asm volatile("cp.async.commit_group;" ::: "memory")
#define CP_WAIT0()  asm volatile("cp.async.wait_group 0;" ::: "memory")

__device__ __forceinline__ void split2(float x0, float x1, uint32_t& h, uint32_t& l) {
    __nv_bfloat16 h0 = __float2bfloat16(x0);
    __nv_bfloat16 h1 = __float2bfloat16(x1);
    __nv_bfloat16 l0 = __float2bfloat16(x0 - __bfloat162float(h0));
    __nv_bfloat16 l1 = __float2bfloat16(x1 - __bfloat162float(h1));
    __nv_bfloat162 hh = __halves2bfloat162(h0, h1);
    __nv_bfloat162 ll = __halves2bfloat162(l0, l1);
    h = *reinterpret_cast<uint32_t*>(&hh);
    l = *reinterpret_cast<uint32_t*>(&ll);
}

// ============ W_gcn split + transpose ============
__global__ __launch_bounds__(256) void wsplit_kernel(const float* __restrict__ Wg)
{
    int idx = blockIdx.x * 256 + threadIdx.x;
    int k = idx >> 8;
    int n = idx & 255;
    float x = Wg[idx];
    __nv_bfloat16 h = __float2bfloat16(x);
    __nv_bfloat16 l = __float2bfloat16(x - __bfloat162float(h));
    g_wt_hi[(size_t)n * DIN + k] = h;
    g_wt_lo[(size_t)n * DIN + k] = l;
}

// ============ W_bil split (element-wise) ============
__global__ __launch_bounds__(256) void wsplit_bil_kernel(const float* __restrict__ Wb)
{
    int idx = blockIdx.x * 256 + threadIdx.x;
    float x = Wb[idx];
    __nv_bfloat16 h = __float2bfloat16(x);
    __nv_bfloat16 l = __float2bfloat16(x - __bfloat162float(h));
    g_wb_hi[idx] = h;
    g_wb_lo[idx] = l;
}

// ============ out init ============
__global__ __launch_bounds__(256) void out_init_kernel(
    const float* __restrict__ b_bil, float* __restrict__ out)
{
    int i = blockIdx.x * 256 + threadIdx.x;
    out[i] = b_bil[0];
}

// ====== GEMM1 fused: 512 thr, double-buffer, B-frag pipeline + cp.async B ======
#define RPAD    80
#define HS      258
#define BUFB    61440
#define OFF_AHI 0
#define OFF_ALO 10240
#define OFF_BHI 20480
#define OFF_BLO 40960
#define OFF_H   0
#define OFF_ADJ (128 * HS * 4)           // 132096
#define OFF_RED (OFF_ADJ + 16 * 64 * 4)  // 136192
#define SMEM_SZ (OFF_RED + 16 * 8 * 2 * 4)  // 137216

__global__ __launch_bounds__(512, 1) void gemm1_fused(
    const float* __restrict__ posx, const float* __restrict__ negx,
    const int* __restrict__ pos_src, const int* __restrict__ pos_dst,
    const float* __restrict__ pos_w,
    const int* __restrict__ neg_src, const int* __restrict__ neg_dst,
    const float* __restrict__ neg_w,
    const float* __restrict__ b_gcn, const float* __restrict__ prelu_a)
{
    extern __shared__ __align__(16) char smem[];
    float* sH   = (float*)(smem + OFF_H);
    float* sAdj = (float*)(smem + OFF_ADJ);
    float* sRed = (float*)(smem + OFF_RED);

    const int tid = threadIdx.x;
    const int wid = tid >> 5;
    const int lane = tid & 31;

    const int m0 = blockIdx.x * 128;
    const int is_pos = (m0 < NNODES);
    const int mloc = is_pos ? m0 : (m0 - NNODES);
    const int warp_m = (wid & 3) * 32;
    const int warp_n = (wid >> 2) * 64;

    const float* X = (is_pos ? posx : negx) + (size_t)mloc * DIN;
    const int*   src = is_pos ? pos_src : neg_src;
    const int*   dst = is_pos ? pos_dst : neg_dst;
    const float* ew  = is_pos ? pos_w   : neg_w;

    const uint32_t sb = smem_u32(smem);

    // ---- build 16 adjacency matrices early ----
    sAdj[tid] = 0.f;
    sAdj[tid + 512] = 0.f;
    __syncthreads();
    {
        const int eb = mloc * 8;
        int2 s2 = *(const int2*)(src + eb + tid * 2);
        int2 d2 = *(const int2*)(dst + eb + tid * 2);
        float2 w2 = *(const float2*)(ew + eb + tid * 2);
        int blk = tid >> 5;
        atomicAdd(&sAdj[blk * 64 + (d2.x & 7) * 8 + (s2.x & 7)], w2.x);
        atomicAdd(&sAdj[blk * 64 + (d2.y & 7) * 8 + (s2.y & 7)], w2.y);
    }

    const int a_lrow = tid >> 2;
    const int a_part = (tid & 3) * 8;
    const float* aptr = X + (size_t)a_lrow * DIN + a_part;
    const uint32_t a_st = (uint32_t)a_lrow * RPAD + (uint32_t)a_part * 2;

    const int b_lrow = tid >> 1;
    const int b_part = (tid & 1) * 16;
    const __nv_bfloat16* bh_ptr = g_wt_hi + (size_t)b_lrow * DIN + b_part;
    const __nv_bfloat16* bl_ptr = g_wt_lo + (size_t)b_lrow * DIN + b_part;
    const uint32_t b_st = (uint32_t)b_lrow * RPAD + (uint32_t)b_part * 2;

    const int a_r  = lane & 15;
    const int a_cg = lane >> 4;
    const int b_t  = lane >> 3;
    const int b_r  = lane & 7;
    const int b_nn = ((b_t >> 1) << 3) + b_r;
    const int b_kk = (b_t & 1) << 3;

    float acc[2][8][4];
    #pragma unroll
    for (int i = 0; i < 2; i++)
        #pragma unroll
        for (int j = 0; j < 8; j++)
            #pragma unroll
            for (int q = 0; q < 4; q++) acc[i][j][q] = 0.f;

    // ---- prologue: A chunk0 -> regs -> buf0; B chunk0 via cp.async -> buf0 ----
    float4 pA0 = *(const float4*)(aptr + 0);
    float4 pA1 = *(const float4*)(aptr + 4);
    {
        const char* bh = (const char*)bh_ptr;
        const char* bl = (const char*)bl_ptr;
        CP_ASYNC16(sb + OFF_BHI + b_st,      bh);
        CP_ASYNC16(sb + OFF_BHI + b_st + 16, bh + 16);
        CP_ASYNC16(sb + OFF_BLO + b_st,      bl);
        CP_ASYNC16(sb + OFF_BLO + b_st + 16, bl + 16);
        CP_COMMIT();
    }
    {
        uint32_t h[4], l[4];
        split2(pA0.x, pA0.y, h[0], l[0]);
        split2(pA0.z, pA0.w, h[1], l[1]);
        split2(pA1.x, pA1.y, h[2], l[2]);
        split2(pA1.z, pA1.w, h[3], l[3]);
        *(uint4*)(smem + OFF_AHI + a_st) = make_uint4(h[0], h[1], h[2], h[3]);
        *(uint4*)(smem + OFF_ALO + a_st) = make_uint4(l[0], l[1], l[2], l[3]);
    }
    CP_WAIT0();
    __syncthreads();

    // 12 MMAs for output group g using fragment regs BH/BL
    #define MMA_GROUP(g, BH, BL) do {                                   \
        _Pragma("unroll")                                               \
        for (int mi = 0; mi < 2; mi++) {                                \
            MMA16816(acc[mi][(g)*2 + 0], ahi[mi], BH[0], BH[1]);        \
            MMA16816(acc[mi][(g)*2 + 1], ahi[mi], BH[2], BH[3]);        \
            MMA16816(acc[mi][(g)*2 + 0], alo[mi], BH[0], BH[1]);        \
            MMA16816(acc[mi][(g)*2 + 1], alo[mi], BH[2], BH[3]);        \
            MMA16816(acc[mi][(g)*2 + 0], ahi[mi], BL[0], BL[1]);        \
            MMA16816(acc[mi][(g)*2 + 1], ahi[mi], BL[2], BL[3]);        \
        } } while (0)

    #define LDB_G(g, BH, BL) do {                                       \
        uint32_t _bo = (uint32_t)(warp_n + (g)*16 + b_nn) * RPAD        \
                     + (uint32_t)(k16 + b_kk) * 2;                      \
        LDSM_X4(BH[0], BH[1], BH[2], BH[3], bhi_b + _bo);               \
        LDSM_X4(BL[0], BL[1], BL[2], BL[3], blo_b + _bo);               \
    } while (0)

    for (int kt = 0; kt < DIN / 32; kt++) {
        const uint32_t cb = (uint32_t)(kt & 1) * BUFB;
        const uint32_t nb = (uint32_t)((kt + 1) & 1) * BUFB;

        // ---- issue next chunk: A LDG -> regs, B cp.async -> alt buffer ----
        if (kt < DIN / 32 - 1) {
            const float* ap = aptr + (kt + 1) * 32;
            pA0 = *(const float4*)(ap + 0);
            pA1 = *(const float4*)(ap + 4);
            const char* bh = (const char*)(bh_ptr + (kt + 1) * 32);
            const char* bl = (const char*)(bl_ptr + (kt + 1) * 32);
            CP_ASYNC16(sb + nb + OFF_BHI + b_st,      bh);
            CP_ASYNC16(sb + nb + OFF_BHI + b_st + 16, bh + 16);
            CP_ASYNC16(sb + nb + OFF_BLO + b_st,      bl);
            CP_ASYNC16(sb + nb + OFF_BLO + b_st + 16, bl + 16);
            CP_COMMIT();
        }

        // ---- compute on buffer cb with B-fragment pipelining ----
        const uint32_t ahi_b = sb + cb + OFF_AHI;
        const uint32_t alo_b = sb + cb + OFF_ALO;
        const uint32_t bhi_b = sb + cb + OFF_BHI;
        const uint32_t blo_b = sb + cb + OFF_BLO;
        #pragma unroll
        for (int k16 = 0; k16 < 32; k16 += 16) {
            uint32_t ahi[2][4], alo[2][4];
            #pragma unroll
            for (int mi = 0; mi < 2; mi++) {
                const uint32_t a_off = (uint32_t)(warp_m + mi * 16 + a_r) * RPAD
                                     + (uint32_t)(k16 + a_cg * 8) * 2;
                LDSM_X4(ahi[mi][0], ahi[mi][1], ahi[mi][2], ahi[mi][3], ahi_b + a_off);
                LDSM_X4(alo[mi][0], alo[mi][1], alo[mi][2], alo[mi][3], alo_b + a_off);
            }
            uint32_t bh0[4], bl0[4], bh1[4], bl1[4];
            LDB_G(0, bh0, bl0);
            LDB_G(1, bh1, bl1);
            MMA_GROUP(0, bh0, bl0);
            LDB_G(2, bh0, bl0);
            MMA_GROUP(1, bh1, bl1);
            LDB_G(3, bh1, bl1);
            MMA_GROUP(2, bh0, bl0);
            MMA_GROUP(3, bh1, bl1);
        }

        // ---- store next A chunk; drain B cp.async ----
        if (kt < DIN / 32 - 1) {
            uint32_t h[4], l[4];
            split2(pA0.x, pA0.y, h[0], l[0]);
            split2(pA0.z, pA0.w, h[1], l[1]);
            split2(pA1.x, pA1.y, h[2], l[2]);
            split2(pA1.z, pA1.w, h[3], l[3]);
            *(uint4*)(smem + nb + OFF_AHI + a_st) = make_uint4(h[0], h[1], h[2], h[3]);
            *(uint4*)(smem + nb + OFF_ALO + a_st) = make_uint4(l[0], l[1], l[2], l[3]);
            CP_WAIT0();
        }
        __syncthreads();
    }

    // ---- epilogue: acc -> smem h (stride HS) ----
    const int er = lane >> 2;
    const int ec = (lane & 3) * 2;
    #pragma unroll
    for (int mi = 0; mi < 2; mi++) {
        #pragma unroll
        for (int nf = 0; nf < 8; nf++) {
            int row = warp_m + mi * 16 + er;
            int col = warp_n + nf * 8 + ec;
            *(float2*)&sH[(size_t)row * HS + col] =
                make_float2(acc[mi][nf][0], acc[mi][nf][1]);
            *(float2*)&sH[(size_t)(row + 8) * HS + col] =
                make_float2(acc[mi][nf][2], acc[mi][nf][3]);
        }
    }
    __syncthreads();

    // ---- agg + PReLU + pool/anchor ----
    const int half = tid >> 8;
    const int col  = tid & 255;
    const int hw   = wid & 7;
    const float pa = prelu_a[0];
    const float bj = b_gcn[col];
    float poolv[8], anchv[8], vp[8], va[8];
    #pragma unroll
    for (int q = 0; q < 8; q++) {
        const int blk = half * 8 + q;
        float x[SS];
        #pragma unroll
        for (int s = 0; s < SS; s++) x[s] = sH[(size_t)(blk * 8 + s) * HS + col];
        float pool = 0.f, anchor = 0.f;
        #pragma unroll
        for (int r = 0; r < SS; r++) {
            float a = bj;
            #pragma unroll
            for (int s = 0; s < SS; s++)
                a = fmaf(sAdj[blk * 64 + r * 8 + s], x[s], a);
            float h = (a >= 0.f) ? a : pa * a;
            if (r < SS - 1) pool += h;
            else            anchor = h;
        }
        pool *= (1.0f / (float)(SS - 1));
        poolv[q] = pool;
        anchv[q] = anchor;
        float p2s = pool * pool, a2s = anchor * anchor;
        #pragma unroll
        for (int o = 16; o; o >>= 1) {
            p2s += __shfl_xor_sync(0xffffffffu, p2s, o);
            a2s += __shfl_xor_sync(0xffffffffu, a2s, o);
        }
        vp[q] = p2s;
        va[q] = a2s;
    }
    if (lane == 0) {
        #pragma unroll
        for (int q = 0; q < 8; q++) {
            const int blk = half * 8 + q;
            sRed[blk * 16 + hw * 2 + 0] = vp[q];
            sRed[blk * 16 + hw * 2 + 1] = va[q];
        }
    }
    __syncthreads();

    const int b0 = mloc / SS;
    #pragma unroll
    for (int q = 0; q < 8; q++) {
        const int blk = half * 8 + q;
        float sp = 0.f, sa = 0.f;
        #pragma unroll
        for (int w = 0; w < 8; w++) {
            sp += sRed[blk * 16 + w * 2 + 0];
            sa += sRed[blk * 16 + w * 2 + 1];
        }
        const float inp = 1.f / fmaxf(sqrtf(sp), 1e-12f);
        const float ina = 1.f / fmaxf(sqrtf(sa), 1e-12f);
        const size_t gi = (size_t)(b0 + blk) * DOUT + col;
        if (is_pos) {
            g_pos_pool[gi] = poolv[q] * inp;
            g_anchor[gi]   = anchv[q] * ina;
        } else {
            g_neg_pool[gi] = poolv[q] * inp;
        }
    }
    #undef MMA_GROUP
    #undef LDB_G
}

// ====== GEMM2 via bf16 3-term mma + fused score, single wave (128 CTAs) ======
#define TS 132
#define G2_AHI 0
#define G2_ALO 10240
#define G2_BHI 20480
#define G2_BLO 30720
#define G2_SMEM (128 * TS * 4)   // 67584

__global__ __launch_bounds__(256, 1) void gemm2_mma(float* __restrict__ out)
{
    extern __shared__ __align__(16) char smem[];
    float* sT = (float*)smem;

    const int tid = threadIdx.x;
    const int wid = tid >> 5;
    const int lane = tid & 31;

    const int m0 = blockIdx.x * 128;
    const int n0 = blockIdx.y * 128;
    const int warp_m = (wid & 3) * 32;
    const int warp_n = (wid >> 2) * 64;

    const uint32_t sb = smem_u32(smem);

    const int a_lrow = tid >> 1;
    const int a_part = (tid & 1) * 16;
    const float* aptr = g_anchor + (size_t)(m0 + a_lrow) * DOUT + a_part;
    const uint32_t a_st = (uint32_t)a_lrow * RPAD + (uint32_t)a_part * 2;

    const int b_lrow = tid >> 1;
    const int b_part = (tid & 1) * 16;
    const __nv_bfloat16* bh_ptr = g_wb_hi + (size_t)(n0 + b_lrow) * DOUT + b_part;
    const __nv_bfloat16* bl_ptr = g_wb_lo + (size_t)(n0 + b_lrow) * DOUT + b_part;
    const uint32_t b_st = (uint32_t)b_lrow * RPAD + (uint32_t)b_part * 2;

    const int a_r  = lane & 15;
    const int a_cg = lane >> 4;
    const int b_t  = lane >> 3;
    const int b_r  = lane & 7;
    const int b_nn = ((b_t >> 1) << 3) + b_r;
    const int b_kk = (b_t & 1) << 3;

    float acc[2][8][4];
    #pragma unroll
    for (int i = 0; i < 2; i++)
        #pragma unroll
        for (int j = 0; j < 8; j++)
            #pragma unroll
            for (int q = 0; q < 4; q++) acc[i][j][q] = 0.f;

    for (int kt = 0; kt < DOUT / 32; kt++) {
        const int k0 = kt * 32;
        {
            const float* ap = aptr + k0;
            float4 v0 = *(const float4*)(ap + 0);
            float4 v1 = *(const float4*)(ap + 4);
            float4 v2 = *(const float4*)(ap + 8);
            float4 v3 = *(const float4*)(ap + 12);
            uint32_t h[8], l[8];
            split2(v0.x, v0.y, h[0], l[0]);
            split2(v0.z, v0.w, h[1], l[1]);
            split2(v1.x, v1.y, h[2], l[2]);
            split2(v1.z, v1.w, h[3], l[3]);
            split2(v2.x, v2.y, h[4], l[4]);
            split2(v2.z, v2.w, h[5], l[5]);
            split2(v3.x, v3.y, h[6], l[6]);
            split2(v3.z, v3.w, h[7], l[7]);
            *(uint4*)(smem + G2_AHI + a_st)      = make_uint4(h[0], h[1], h[2], h[3]);
            *(uint4*)(smem + G2_AHI + a_st + 16) = make_uint4(h[4], h[5], h[6], h[7]);
            *(uint4*)(smem + G2_ALO + a_st)      = make_uint4(l[0], l[1], l[2], l[3]);
            *(uint4*)(smem + G2_ALO + a_st + 16) = make_uint4(l[4], l[5], l[6], l[7]);
        }
        {
            const char* bh = (const char*)(bh_ptr + k0);
            const char* bl = (const char*)(bl_ptr + k0);
            uint4 h0 = *(const uint4*)(bh);
            uint4 h1 = *(const uint4*)(bh + 16);
            uint4 l0 = *(const uint4*)(bl);
            uint4 l1 = *(const uint4*)(bl + 16);
            *(uint4*)(smem + G2_BHI + b_st)      = h0;
            *(uint4*)(smem + G2_BHI + b_st + 16) = h1;
            *(uint4*)(smem + G2_BLO + b_st)      = l0;
            *(uint4*)(smem + G2_BLO + b_st + 16) = l1;
        }
        __syncthreads();

        #pragma unroll
        for (int k16 = 0; k16 < 32; k16 += 16) {
            uint32_t ahi[2][4], alo[2][4];
            #pragma unroll
            for (int mi = 0; mi < 2; mi++) {
                const uint32_t a_off = (uint32_t)(warp_m + mi * 16 + a_r) * RPAD
                                     + (uint32_t)(k16 + a_cg * 8) * 2;
                LDSM_X4(ahi[mi][0], ahi[mi][1], ahi[mi][2], ahi[mi][3], sb + G2_AHI + a_off);
                LDSM_X4(alo[mi][0], alo[mi][1], alo[mi][2], alo[mi][3], sb + G2_ALO + a_off);
            }
            #pragma unroll
            for (int g = 0; g < 4; g++) {
                const uint32_t b_off = (uint32_t)(warp_n + g * 16 + b_nn) * RPAD
                                     + (uint32_t)(k16 + b_kk) * 2;
                uint32_t bh[4], bl[4];
                LDSM_X4(bh[0], bh[1], bh[2], bh[3], sb + G2_BHI + b_off);
                LDSM_X4(bl[0], bl[1], bl[2], bl[3], sb + G2_BLO + b_off);
                #pragma unroll
                for (int mi = 0; mi < 2; mi++) {
                    MMA16816(acc[mi][g * 2 + 0], ahi[mi], bh[0], bh[1]);
                    MMA16816(acc[mi][g * 2 + 1], ahi[mi], bh[2], bh[3]);
                    MMA16816(acc[mi][g * 2 + 0], alo[mi], bh[0], bh[1]);
                    MMA16816(acc[mi][g * 2 + 1], alo[mi], bh[2], bh[3]);
                    MMA16816(acc[mi][g * 2 + 0], ahi[mi], bl[0], bl[1]);
                    MMA16816(acc[mi][g * 2 + 1], ahi[mi], bl[2], bl[3]);
                }
            }
        }
        __syncthreads();
    }

    // ---- T tile -> smem ----
    const int er = lane >> 2;
    const int ec = (lane & 3) * 2;
    #pragma unroll
    for (int mi = 0; mi < 2; mi++) {
        #pragma unroll
        for (int nf = 0; nf < 8; nf++) {
            int row = warp_m + mi * 16 + er;
            int col = warp_n + nf * 8 + ec;
            *(float2*)&sT[(size_t)row * TS + col] =
                make_float2(acc[mi][nf][0], acc[mi][nf][1]);
            *(float2*)&sT[(size_t)(row + 8) * TS + col] =
                make_float2(acc[mi][nf][2], acc[mi][nf][3]);
        }
    }
    __syncthreads();

    // ---- fused score ----
    #pragma unroll
    for (int rr = 0; rr < 16; rr++) {
        const int r = wid * 16 + rr;
        const int grow = m0 + r;
        const float* pp = g_pos_pool + (size_t)grow * DOUT + n0;
        const float* np = g_neg_pool + (size_t)grow * DOUT + n0;
        float sp = 0.f, sn = 0.f;
        #pragma unroll
        for (int q = 0; q < 4; q++) {
            float t = sT[(size_t)r * TS + lane + q * 32];
            sp = fmaf(t, pp[lane + q * 32], sp);
            sn = fmaf(t, np[lane + q * 32], sn);
        }
        #pragma unroll
        for (int o = 16; o; o >>= 1) {
            sp += __shfl_xor_sync(0xffffffffu, sp, o);
            sn += __shfl_xor_sync(0xffffffffu, sn, o);
        }
        if (lane == 0) {
            atomicAdd(&out[grow], sp);
            atomicAdd(&out[NB + grow], sn);
        }
    }
}

extern "C" void kernel_launch(void* const* d_in, const int* in_sizes, int n_in,
                              void* d_out, int out_size)
{
    const float* pos_x   = (const float*)d_in[0];
    const float* neg_x   = (const float*)d_in[1];
    const int*   pos_src = (const int*)d_in[2];
    const int*   pos_dst = (const int*)d_in[3];
    const float* pos_w   = (const float*)d_in[4];
    const int*   neg_src = (const int*)d_in[5];
    const int*   neg_dst = (const int*)d_in[6];
    const float* neg_w   = (const float*)d_in[7];
    const float* W_gcn   = (const float*)d_in[8];
    const float* b_gcn   = (const float*)d_in[9];
    const float* prelu_a = (const float*)d_in[10];
    const float* W_bil   = (const float*)d_in[11];
    const float* b_bil   = (const float*)d_in[12];
    float* out = (float*)d_out;

    (void)in_sizes; (void)n_in; (void)out_size;

    cudaFuncSetAttribute(gemm1_fused, cudaFuncAttributeMaxDynamicSharedMemorySize,
                         SMEM_SZ);
    cudaFuncSetAttribute(gemm2_mma, cudaFuncAttributeMaxDynamicSharedMemorySize,
                         G2_SMEM);

    // 0) weight splits + out init
    wsplit_kernel<<<512, 256>>>(W_gcn);
    wsplit_bil_kernel<<<256, 256>>>(W_bil);
    out_init_kernel<<<2 * NB / 256, 256>>>(b_bil, out);

    // 1) fused: xw GEMM + agg + PReLU + pool + anchor + L2 norm
    gemm1_fused<<<2 * NNODES / 128, 512, SMEM_SZ>>>(
        pos_x, neg_x, pos_src, pos_dst, pos_w,
        neg_src, neg_dst, neg_w, b_gcn, prelu_a);

    // 2) T = anchor @ W_bil^T (bf16 3-term mma) + fused scores
    gemm2_mma<<<dim3(NB / 128, DOUT / 128), 256, G2_SMEM>>>(out);
}

// round 15
// speedup vs baseline: 1.4032x; 1.4032x over previous
#include <cuda_runtime.h>
#include <cuda_bf16.h>
#include <cstdint>
#include <math.h>

#define NNODES 65536   // nodes per branch (B*S)
#define NB     8192    // graph blocks
#define SS     8       // nodes per block
#define EPB    64      // edges per block
#define DIN    512
#define DOUT   256

// ---- scratch (static device globals; no allocation allowed) ----
__device__ float g_pos_pool[NB * DOUT];
__device__ float g_neg_pool[NB * DOUT];
__device__ float g_anchor[NB * DOUT];
__device__ __nv_bfloat16 g_wt_hi[DOUT * DIN];   // W_gcn^T split-hi [256][512]
__device__ __nv_bfloat16 g_wt_lo[DOUT * DIN];   // W_gcn^T split-lo
__device__ __nv_bfloat16 g_wb_hi[DOUT * DOUT];  // W_bil split-hi [256][256]
__device__ __nv_bfloat16 g_wb_lo[DOUT * DOUT];  // W_bil split-lo

// ======================= helpers =======================
__device__ __forceinline__ uint32_t smem_u32(const void* p) {
    uint32_t a;
    asm("{ .reg .u64 t; cvta.to.shared.u64 t, %1; cvt.u32.u64 %0, t; }"
        : "=r"(a) : "l"(p));
    return a;
}

#define LDSM_X4(r0, r1, r2, r3, addr) \
    asm volatile("ldmatrix.sync.aligned.m8n8.x4.shared.b16 {%0,%1,%2,%3}, [%4];" \
        : "=r"(r0), "=r"(r1), "=r"(r2), "=r"(r3) : "r"(addr))

#define MMA16816(d, a, b0, b1) \
    asm volatile("mma.sync.aligned.m16n8k16.row.col.f32.bf16.bf16.f32 " \
        "{%0,%1,%2,%3}, {%4,%5,%6,%7}, {%8,%9}, {%0,%1,%2,%3};" \
        : "+f"((d)[0]), "+f"((d)[1]), "+f"((d)[2]), "+f"((d)[3]) \
        : "r"((a)[0]), "r"((a)[1]), "r"((a)[2]), "r"((a)[3]), "r"(b0), "r"(b1))

__device__ __forceinline__ void split2(float x0, float x1, uint32_t& h, uint32_t& l) {
    __nv_bfloat16 h0 = __float2bfloat16(x0);
    __nv_bfloat16 h1 = __float2bfloat16(x1);
    __nv_bfloat16 l0 = __float2bfloat16(x0 - __bfloat162float(h0));
    __nv_bfloat16 l1 = __float2bfloat16(x1 - __bfloat162float(h1));
    __nv_bfloat162 hh = __halves2bfloat162(h0, h1);
    __nv_bfloat162 ll = __halves2bfloat162(l0, l1);
    h = *reinterpret_cast<uint32_t*>(&hh);
    l = *reinterpret_cast<uint32_t*>(&ll);
}

// ===== combined prologue: W_gcn split+transpose, W_bil split, out init =====
// blocks 0..511   -> W_gcn (131072 elems)
// blocks 512..767 -> W_bil (65536 elems)
// blocks 768..831 -> out   (16384 elems)
__global__ __launch_bounds__(256) void prologue_kernel(
    const float* __restrict__ Wg, const float* __restrict__ Wb,
    const float* __restrict__ b_bil, float* __restrict__ out)
{
    const int bx = blockIdx.x;
    if (bx < 512) {
        int idx = bx * 256 + threadIdx.x;
        int k = idx >> 8;
        int n = idx & 255;
        float x = Wg[idx];
        __nv_bfloat16 h = __float2bfloat16(x);
        __nv_bfloat16 l = __float2bfloat16(x - __bfloat162float(h));
        g_wt_hi[(size_t)n * DIN + k] = h;
        g_wt_lo[(size_t)n * DIN + k] = l;
    } else if (bx < 768) {
        int idx = (bx - 512) * 256 + threadIdx.x;
        float x = Wb[idx];
        __nv_bfloat16 h = __float2bfloat16(x);
        __nv_bfloat16 l = __float2bfloat16(x - __bfloat162float(h));
        g_wb_hi[idx] = h;
        g_wb_lo[idx] = l;
    } else {
        int idx = (bx - 768) * 256 + threadIdx.x;   // 0..16383 = 2*NB
        out[idx] = b_bil[0];
    }
}

// ====== GEMM1 fused, 512 threads, double-buffered tiles + agg epilogue ======
#define RPAD    80
#define HS      258
#define BUFB    61440
#define OFF_AHI 0
#define OFF_ALO 10240
#define OFF_BHI 20480
#define OFF_BLO 40960
#define OFF_H   0
#define OFF_ADJ (128 * HS * 4)           // 132096
#define OFF_RED (OFF_ADJ + 16 * 64 * 4)  // 136192
#define SMEM_SZ (OFF_RED + 16 * 8 * 2 * 4)  // 137216

__global__ __launch_bounds__(512, 1) void gemm1_fused(
    const float* __restrict__ posx, const float* __restrict__ negx,
    const int* __restrict__ pos_src, const int* __restrict__ pos_dst,
    const float* __restrict__ pos_w,
    const int* __restrict__ neg_src, const int* __restrict__ neg_dst,
    const float* __restrict__ neg_w,
    const float* __restrict__ b_gcn, const float* __restrict__ prelu_a)
{
    extern __shared__ __align__(16) char smem[];
    float* sH   = (float*)(smem + OFF_H);
    float* sAdj = (float*)(smem + OFF_ADJ);
    float* sRed = (float*)(smem + OFF_RED);

    const int tid = threadIdx.x;
    const int wid = tid >> 5;
    const int lane = tid & 31;

    const int m0 = blockIdx.x * 128;
    const int is_pos = (m0 < NNODES);
    const int mloc = is_pos ? m0 : (m0 - NNODES);
    const int warp_m = (wid & 3) * 32;
    const int warp_n = (wid >> 2) * 64;

    const float* X = (is_pos ? posx : negx) + (size_t)mloc * DIN;
    const int*   src = is_pos ? pos_src : neg_src;
    const int*   dst = is_pos ? pos_dst : neg_dst;
    const float* ew  = is_pos ? pos_w   : neg_w;

    const uint32_t sb = smem_u32(smem);

    // ---- build 16 adjacency matrices early ----
    sAdj[tid] = 0.f;
    sAdj[tid + 512] = 0.f;
    __syncthreads();
    {
        const int eb = mloc * 8;
        int2 s2 = *(const int2*)(src + eb + tid * 2);
        int2 d2 = *(const int2*)(dst + eb + tid * 2);
        float2 w2 = *(const float2*)(ew + eb + tid * 2);
        int blk = tid >> 5;
        atomicAdd(&sAdj[blk * 64 + (d2.x & 7) * 8 + (s2.x & 7)], w2.x);
        atomicAdd(&sAdj[blk * 64 + (d2.y & 7) * 8 + (s2.y & 7)], w2.y);
    }

    const int a_lrow = tid >> 2;
    const int a_part = (tid & 3) * 8;
    const float* aptr = X + (size_t)a_lrow * DIN + a_part;
    const uint32_t a_st = (uint32_t)a_lrow * RPAD + (uint32_t)a_part * 2;

    const int b_lrow = tid >> 1;
    const int b_part = (tid & 1) * 16;
    const __nv_bfloat16* bh_ptr = g_wt_hi + (size_t)b_lrow * DIN + b_part;
    const __nv_bfloat16* bl_ptr = g_wt_lo + (size_t)b_lrow * DIN + b_part;
    const uint32_t b_st = (uint32_t)b_lrow * RPAD + (uint32_t)b_part * 2;

    const int a_r  = lane & 15;
    const int a_cg = lane >> 4;
    const int b_t  = lane >> 3;
    const int b_r  = lane & 7;
    const int b_nn = ((b_t >> 1) << 3) + b_r;
    const int b_kk = (b_t & 1) << 3;

    float acc[2][8][4];
    #pragma unroll
    for (int i = 0; i < 2; i++)
        #pragma unroll
        for (int j = 0; j < 8; j++)
            #pragma unroll
            for (int q = 0; q < 4; q++) acc[i][j][q] = 0.f;

    float4 pA0 = *(const float4*)(aptr + 0);
    float4 pA1 = *(const float4*)(aptr + 4);
    uint4 pBh0 = *(const uint4*)((const char*)bh_ptr);
    uint4 pBh1 = *(const uint4*)((const char*)bh_ptr + 16);
    uint4 pBl0 = *(const uint4*)((const char*)bl_ptr);
    uint4 pBl1 = *(const uint4*)((const char*)bl_ptr + 16);
    {
        uint32_t h[4], l[4];
        split2(pA0.x, pA0.y, h[0], l[0]);
        split2(pA0.z, pA0.w, h[1], l[1]);
        split2(pA1.x, pA1.y, h[2], l[2]);
        split2(pA1.z, pA1.w, h[3], l[3]);
        *(uint4*)(smem + OFF_AHI + a_st) = make_uint4(h[0], h[1], h[2], h[3]);
        *(uint4*)(smem + OFF_ALO + a_st) = make_uint4(l[0], l[1], l[2], l[3]);
        *(uint4*)(smem + OFF_BHI + b_st)      = pBh0;
        *(uint4*)(smem + OFF_BHI + b_st + 16) = pBh1;
        *(uint4*)(smem + OFF_BLO + b_st)      = pBl0;
        *(uint4*)(smem + OFF_BLO + b_st + 16) = pBl1;
    }
    __syncthreads();

    for (int kt = 0; kt < DIN / 32; kt++) {
        const uint32_t cb = (uint32_t)(kt & 1) * BUFB;

        if (kt < DIN / 32 - 1) {
            const float* ap = aptr + (kt + 1) * 32;
            pA0 = *(const float4*)(ap + 0);
            pA1 = *(const float4*)(ap + 4);
            const char* bh = (const char*)(bh_ptr + (kt + 1) * 32);
            const char* bl = (const char*)(bl_ptr + (kt + 1) * 32);
            pBh0 = *(const uint4*)(bh);
            pBh1 = *(const uint4*)(bh + 16);
            pBl0 = *(const uint4*)(bl);
            pBl1 = *(const uint4*)(bl + 16);
        }

        const uint32_t ahi_b = sb + cb + OFF_AHI;
        const uint32_t alo_b = sb + cb + OFF_ALO;
        const uint32_t bhi_b = sb + cb + OFF_BHI;
        const uint32_t blo_b = sb + cb + OFF_BLO;
        #pragma unroll
        for (int k16 = 0; k16 < 32; k16 += 16) {
            uint32_t ahi[2][4], alo[2][4];
            #pragma unroll
            for (int mi = 0; mi < 2; mi++) {
                const uint32_t a_off = (uint32_t)(warp_m + mi * 16 + a_r) * RPAD
                                     + (uint32_t)(k16 + a_cg * 8) * 2;
                LDSM_X4(ahi[mi][0], ahi[mi][1], ahi[mi][2], ahi[mi][3], ahi_b + a_off);
                LDSM_X4(alo[mi][0], alo[mi][1], alo[mi][2], alo[mi][3], alo_b + a_off);
            }
            #pragma unroll
            for (int g = 0; g < 4; g++) {
                const uint32_t b_off = (uint32_t)(warp_n + g * 16 + b_nn) * RPAD
                                     + (uint32_t)(k16 + b_kk) * 2;
                uint32_t bh[4], bl[4];
                LDSM_X4(bh[0], bh[1], bh[2], bh[3], bhi_b + b_off);
                LDSM_X4(bl[0], bl[1], bl[2], bl[3], blo_b + b_off);
                #pragma unroll
                for (int mi = 0; mi < 2; mi++) {
                    MMA16816(acc[mi][g * 2 + 0], ahi[mi], bh[0], bh[1]);
                    MMA16816(acc[mi][g * 2 + 1], ahi[mi], bh[2], bh[3]);
                    MMA16816(acc[mi][g * 2 + 0], alo[mi], bh[0], bh[1]);
                    MMA16816(acc[mi][g * 2 + 1], alo[mi], bh[2], bh[3]);
                    MMA16816(acc[mi][g * 2 + 0], ahi[mi], bl[0], bl[1]);
                    MMA16816(acc[mi][g * 2 + 1], ahi[mi], bl[2], bl[3]);
                }
            }
        }

        if (kt < DIN / 32 - 1) {
            const uint32_t nb = (uint32_t)((kt + 1) & 1) * BUFB;
            uint32_t h[4], l[4];
            split2(pA0.x, pA0.y, h[0], l[0]);
            split2(pA0.z, pA0.w, h[1], l[1]);
            split2(pA1.x, pA1.y, h[2], l[2]);
            split2(pA1.z, pA1.w, h[3], l[3]);
            *(uint4*)(smem + nb + OFF_AHI + a_st) = make_uint4(h[0], h[1], h[2], h[3]);
            *(uint4*)(smem + nb + OFF_ALO + a_st) = make_uint4(l[0], l[1], l[2], l[3]);
            *(uint4*)(smem + nb + OFF_BHI + b_st)      = pBh0;
            *(uint4*)(smem + nb + OFF_BHI + b_st + 16) = pBh1;
            *(uint4*)(smem + nb + OFF_BLO + b_st)      = pBl0;
            *(uint4*)(smem + nb + OFF_BLO + b_st + 16) = pBl1;
        }
        __syncthreads();
    }

    // ---- epilogue: acc -> smem h (stride HS) ----
    const int er = lane >> 2;
    const int ec = (lane & 3) * 2;
    #pragma unroll
    for (int mi = 0; mi < 2; mi++) {
        #pragma unroll
        for (int nf = 0; nf < 8; nf++) {
            int row = warp_m + mi * 16 + er;
            int col = warp_n + nf * 8 + ec;
            *(float2*)&sH[(size_t)row * HS + col] =
                make_float2(acc[mi][nf][0], acc[mi][nf][1]);
            *(float2*)&sH[(size_t)(row + 8) * HS + col] =
                make_float2(acc[mi][nf][2], acc[mi][nf][3]);
        }
    }
    __syncthreads();

    // ---- agg + PReLU + pool/anchor ----
    const int half = tid >> 8;
    const int col  = tid & 255;
    const int hw   = wid & 7;
    const float pa = prelu_a[0];
    const float bj = b_gcn[col];
    float poolv[8], anchv[8], vp[8], va[8];
    #pragma unroll
    for (int q = 0; q < 8; q++) {
        const int blk = half * 8 + q;
        float x[SS];
        #pragma unroll
        for (int s = 0; s < SS; s++) x[s] = sH[(size_t)(blk * 8 + s) * HS + col];
        float pool = 0.f, anchor = 0.f;
        #pragma unroll
        for (int r = 0; r < SS; r++) {
            float a = bj;
            #pragma unroll
            for (int s = 0; s < SS; s++)
                a = fmaf(sAdj[blk * 64 + r * 8 + s], x[s], a);
            float h = (a >= 0.f) ? a : pa * a;
            if (r < SS - 1) pool += h;
            else            anchor = h;
        }
        pool *= (1.0f / (float)(SS - 1));
        poolv[q] = pool;
        anchv[q] = anchor;
        float p2s = pool * pool, a2s = anchor * anchor;
        #pragma unroll
        for (int o = 16; o; o >>= 1) {
            p2s += __shfl_xor_sync(0xffffffffu, p2s, o);
            a2s += __shfl_xor_sync(0xffffffffu, a2s, o);
        }
        vp[q] = p2s;
        va[q] = a2s;
    }
    if (lane == 0) {
        #pragma unroll
        for (int q = 0; q < 8; q++) {
            const int blk = half * 8 + q;
            sRed[blk * 16 + hw * 2 + 0] = vp[q];
            sRed[blk * 16 + hw * 2 + 1] = va[q];
        }
    }
    __syncthreads();

    const int b0 = mloc / SS;
    #pragma unroll
    for (int q = 0; q < 8; q++) {
        const int blk = half * 8 + q;
        float sp = 0.f, sa = 0.f;
        #pragma unroll
        for (int w = 0; w < 8; w++) {
            sp += sRed[blk * 16 + w * 2 + 0];
            sa += sRed[blk * 16 + w * 2 + 1];
        }
        const float inp = 1.f / fmaxf(sqrtf(sp), 1e-12f);
        const float ina = 1.f / fmaxf(sqrtf(sa), 1e-12f);
        const size_t gi = (size_t)(b0 + blk) * DOUT + col;
        if (is_pos) {
            g_pos_pool[gi] = poolv[q] * inp;
            g_anchor[gi]   = anchv[q] * ina;
        } else {
            g_neg_pool[gi] = poolv[q] * inp;
        }
    }
}

// ====== GEMM2 via bf16 3-term mma + fused score, single wave (128 CTAs) ======
#define TS 132
#define G2_AHI 0
#define G2_ALO 10240
#define G2_BHI 20480
#define G2_BLO 30720
#define G2_SMEM (128 * TS * 4)   // 67584

__global__ __launch_bounds__(256, 1) void gemm2_mma(float* __restrict__ out)
{
    extern __shared__ __align__(16) char smem[];
    float* sT = (float*)smem;

    const int tid = threadIdx.x;
    const int wid = tid >> 5;
    const int lane = tid & 31;

    const int m0 = blockIdx.x * 128;
    const int n0 = blockIdx.y * 128;
    const int warp_m = (wid & 3) * 32;
    const int warp_n = (wid >> 2) * 64;

    const uint32_t sb = smem_u32(smem);

    const int a_lrow = tid >> 1;
    const int a_part = (tid & 1) * 16;
    const float* aptr = g_anchor + (size_t)(m0 + a_lrow) * DOUT + a_part;
    const uint32_t a_st = (uint32_t)a_lrow * RPAD + (uint32_t)a_part * 2;

    const int b_lrow = tid >> 1;
    const int b_part = (tid & 1) * 16;
    const __nv_bfloat16* bh_ptr = g_wb_hi + (size_t)(n0 + b_lrow) * DOUT + b_part;
    const __nv_bfloat16* bl_ptr = g_wb_lo + (size_t)(n0 + b_lrow) * DOUT + b_part;
    const uint32_t b_st = (uint32_t)b_lrow * RPAD + (uint32_t)b_part * 2;

    const int a_r  = lane & 15;
    const int a_cg = lane >> 4;
    const int b_t  = lane >> 3;
    const int b_r  = lane & 7;
    const int b_nn = ((b_t >> 1) << 3) + b_r;
    const int b_kk = (b_t & 1) << 3;

    float acc[2][8][4];
    #pragma unroll
    for (int i = 0; i < 2; i++)
        #pragma unroll
        for (int j = 0; j < 8; j++)
            #pragma unroll
            for (int q = 0; q < 4; q++) acc[i][j][q] = 0.f;

    for (int kt = 0; kt < DOUT / 32; kt++) {
        const int k0 = kt * 32;
        {
            const float* ap = aptr + k0;
            float4 v0 = *(const float4*)(ap + 0);
            float4 v1 = *(const float4*)(ap + 4);
            float4 v2 = *(const float4*)(ap + 8);
            float4 v3 = *(const float4*)(ap + 12);
            uint32_t h[8], l[8];
            split2(v0.x, v0.y, h[0], l[0]);
            split2(v0.z, v0.w, h[1], l[1]);
            split2(v1.x, v1.y, h[2], l[2]);
            split2(v1.z, v1.w, h[3], l[3]);
            split2(v2.x, v2.y, h[4], l[4]);
            split2(v2.z, v2.w, h[5], l[5]);
            split2(v3.x, v3.y, h[6], l[6]);
            split2(v3.z, v3.w, h[7], l[7]);
            *(uint4*)(smem + G2_AHI + a_st)      = make_uint4(h[0], h[1], h[2], h[3]);
            *(uint4*)(smem + G2_AHI + a_st + 16) = make_uint4(h[4], h[5], h[6], h[7]);
            *(uint4*)(smem + G2_ALO + a_st)      = make_uint4(l[0], l[1], l[2], l[3]);
            *(uint4*)(smem + G2_ALO + a_st + 16) = make_uint4(l[4], l[5], l[6], l[7]);
        }
        {
            const char* bh = (const char*)(bh_ptr + k0);
            const char* bl = (const char*)(bl_ptr + k0);
            uint4 h0 = *(const uint4*)(bh);
            uint4 h1 = *(const uint4*)(bh + 16);
            uint4 l0 = *(const uint4*)(bl);
            uint4 l1 = *(const uint4*)(bl + 16);
            *(uint4*)(smem + G2_BHI + b_st)      = h0;
            *(uint4*)(smem + G2_BHI + b_st + 16) = h1;
            *(uint4*)(smem + G2_BLO + b_st)      = l0;
            *(uint4*)(smem + G2_BLO + b_st + 16) = l1;
        }
        __syncthreads();

        #pragma unroll
        for (int k16 = 0; k16 < 32; k16 += 16) {
            uint32_t ahi[2][4], alo[2][4];
            #pragma unroll
            for (int mi = 0; mi < 2; mi++) {
                const uint32_t a_off = (uint32_t)(warp_m + mi * 16 + a_r) * RPAD
                                     + (uint32_t)(k16 + a_cg * 8) * 2;
                LDSM_X4(ahi[mi][0], ahi[mi][1], ahi[mi][2], ahi[mi][3], sb + G2_AHI + a_off);
                LDSM_X4(alo[mi][0], alo[mi][1], alo[mi][2], alo[mi][3], sb + G2_ALO + a_off);
            }
            #pragma unroll
            for (int g = 0; g < 4; g++) {
                const uint32_t b_off = (uint32_t)(warp_n + g * 16 + b_nn) * RPAD
                                     + (uint32_t)(k16 + b_kk) * 2;
                uint32_t bh[4], bl[4];
                LDSM_X4(bh[0], bh[1], bh[2], bh[3], sb + G2_BHI + b_off);
                LDSM_X4(bl[0], bl[1], bl[2], bl[3], sb + G2_BLO + b_off);
                #pragma unroll
                for (int mi = 0; mi < 2; mi++) {
                    MMA16816(acc[mi][g * 2 + 0], ahi[mi], bh[0], bh[1]);
                    MMA16816(acc[mi][g * 2 + 1], ahi[mi], bh[2], bh[3]);
                    MMA16816(acc[mi][g * 2 + 0], alo[mi], bh[0], bh[1]);
                    MMA16816(acc[mi][g * 2 + 1], alo[mi], bh[2], bh[3]);
                    MMA16816(acc[mi][g * 2 + 0], ahi[mi], bl[0], bl[1]);
                    MMA16816(acc[mi][g * 2 + 1], ahi[mi], bl[2], bl[3]);
                }
            }
        }
        __syncthreads();
    }

    // ---- T tile -> smem ----
    const int er = lane >> 2;
    const int ec = (lane & 3) * 2;
    #pragma unroll
    for (int mi = 0; mi < 2; mi++) {
        #pragma unroll
        for (int nf = 0; nf < 8; nf++) {
            int row = warp_m + mi * 16 + er;
            int col = warp_n + nf * 8 + ec;
            *(float2*)&sT[(size_t)row * TS + col] =
                make_float2(acc[mi][nf][0], acc[mi][nf][1]);
            *(float2*)&sT[(size_t)(row + 8) * TS + col] =
                make_float2(acc[mi][nf][2], acc[mi][nf][3]);
        }
    }
    __syncthreads();

    // ---- fused score ----
    #pragma unroll
    for (int rr = 0; rr < 16; rr++) {
        const int r = wid * 16 + rr;
        const int grow = m0 + r;
        const float* pp = g_pos_pool + (size_t)grow * DOUT + n0;
        const float* np = g_neg_pool + (size_t)grow * DOUT + n0;
        float sp = 0.f, sn = 0.f;
        #pragma unroll
        for (int q = 0; q < 4; q++) {
            float t = sT[(size_t)r * TS + lane + q * 32];
            sp = fmaf(t, pp[lane + q * 32], sp);
            sn = fmaf(t, np[lane + q * 32], sn);
        }
        #pragma unroll
        for (int o = 16; o; o >>= 1) {
            sp += __shfl_xor_sync(0xffffffffu, sp, o);
            sn += __shfl_xor_sync(0xffffffffu, sn, o);
        }
        if (lane == 0) {
            atomicAdd(&out[grow], sp);
            atomicAdd(&out[NB + grow], sn);
        }
    }
}

extern "C" void kernel_launch(void* const* d_in, const int* in_sizes, int n_in,
                              void* d_out, int out_size)
{
    const float* pos_x   = (const float*)d_in[0];
    const float* neg_x   = (const float*)d_in[1];
    const int*   pos_src = (const int*)d_in[2];
    const int*   pos_dst = (const int*)d_in[3];
    const float* pos_w   = (const float*)d_in[4];
    const int*   neg_src = (const int*)d_in[5];
    const int*   neg_dst = (const int*)d_in[6];
    const float* neg_w   = (const float*)d_in[7];
    const float* W_gcn   = (const float*)d_in[8];
    const float* b_gcn   = (const float*)d_in[9];
    const float* prelu_a = (const float*)d_in[10];
    const float* W_bil   = (const float*)d_in[11];
    const float* b_bil   = (const float*)d_in[12];
    float* out = (float*)d_out;

    (void)in_sizes; (void)n_in; (void)out_size;

    cudaFuncSetAttribute(gemm1_fused, cudaFuncAttributeMaxDynamicSharedMemorySize,
                         SMEM_SZ);
    cudaFuncSetAttribute(gemm2_mma, cudaFuncAttributeMaxDynamicSharedMemorySize,
                         G2_SMEM);

    // 0) combined prologue: weight splits + out init (one launch)
    prologue_kernel<<<832, 256>>>(W_gcn, W_bil, b_bil, out);

    // 1) fused: xw GEMM + agg + PReLU + pool + anchor + L2 norm
    gemm1_fused<<<2 * NNODES / 128, 512, SMEM_SZ>>>(
        pos_x, neg_x, pos_src, pos_dst, pos_w,
        neg_src, neg_dst, neg_w, b_gcn, prelu_a);

    // 2) T = anchor @ W_bil^T (bf16 3-term mma) + fused scores
    gemm2_mma<<<dim3(NB / 128, DOUT / 128), 256, G2_SMEM>>>(out);
}

// round 16
// speedup vs baseline: 1.4188x; 1.0112x over previous
#include <cuda_runtime.h>
#include <cuda_bf16.h>
#include <cstdint>
#include <math.h>

#define NNODES 65536   // nodes per branch (B*S)
#define NB     8192    // graph blocks
#define SS     8       // nodes per block
#define EPB    64      // edges per block
#define DIN    512
#define DOUT   256

// ---- scratch (static device globals; no allocation allowed) ----
__device__ float g_pos_pool[NB * DOUT];
__device__ float g_neg_pool[NB * DOUT];
__device__ float g_anchor[NB * DOUT];
__device__ __nv_bfloat16 g_wt_hi[DOUT * DIN];   // W_gcn^T split-hi [256][512]
__device__ __nv_bfloat16 g_wt_lo[DOUT * DIN];   // W_gcn^T split-lo
__device__ __nv_bfloat16 g_wb_hi[DOUT * DOUT];  // W_bil split-hi [256][256]
__device__ __nv_bfloat16 g_wb_lo[DOUT * DOUT];  // W_bil split-lo

// ======================= helpers =======================
__device__ __forceinline__ uint32_t smem_u32(const void* p) {
    uint32_t a;
    asm("{ .reg .u64 t; cvta.to.shared.u64 t, %1; cvt.u32.u64 %0, t; }"
        : "=r"(a) : "l"(p));
    return a;
}

#define LDSM_X4(r0, r1, r2, r3, addr) \
    asm volatile("ldmatrix.sync.aligned.m8n8.x4.shared.b16 {%0,%1,%2,%3}, [%4];" \
        : "=r"(r0), "=r"(r1), "=r"(r2), "=r"(r3) : "r"(addr))

#define MMA16816(d, a, b0, b1) \
    asm volatile("mma.sync.aligned.m16n8k16.row.col.f32.bf16.bf16.f32 " \
        "{%0,%1,%2,%3}, {%4,%5,%6,%7}, {%8,%9}, {%0,%1,%2,%3};" \
        : "+f"((d)[0]), "+f"((d)[1]), "+f"((d)[2]), "+f"((d)[3]) \
        : "r"((a)[0]), "r"((a)[1]), "r"((a)[2]), "r"((a)[3]), "r"(b0), "r"(b1))

__device__ __forceinline__ void split2(float x0, float x1, uint32_t& h, uint32_t& l) {
    __nv_bfloat16 h0 = __float2bfloat16(x0);
    __nv_bfloat16 h1 = __float2bfloat16(x1);
    __nv_bfloat16 l0 = __float2bfloat16(x0 - __bfloat162float(h0));
    __nv_bfloat16 l1 = __float2bfloat16(x1 - __bfloat162float(h1));
    __nv_bfloat162 hh = __halves2bfloat162(h0, h1);
    __nv_bfloat162 ll = __halves2bfloat162(l0, l1);
    h = *reinterpret_cast<uint32_t*>(&hh);
    l = *reinterpret_cast<uint32_t*>(&ll);
}

// ===== combined prologue (coalesced): W_gcn tile-transpose split, W_bil split, out init =====
// blocks 0..31    -> W_gcn transpose+split via 64x64 smem tiles (coalesced both sides)
// blocks 32..287  -> W_bil element-wise split (65536 elems)
// blocks 288..351 -> out init (16384 elems)
__global__ __launch_bounds__(256) void prologue_kernel(
    const float* __restrict__ Wg, const float* __restrict__ Wb,
    const float* __restrict__ b_bil, float* __restrict__ out)
{
    const int bx = blockIdx.x;
    if (bx < 32) {
        __shared__ float tile[64][65];
        const int k0 = (bx >> 2) * 64;      // 8 k-tiles
        const int n0 = (bx & 3) * 64;       // 4 n-tiles
        const int col = threadIdx.x & 63;
        const int rb  = threadIdx.x >> 6;   // 0..3
        #pragma unroll
        for (int i = 0; i < 16; i++) {
            int row = rb + i * 4;
            tile[row][col] = Wg[(size_t)(k0 + row) * DOUT + n0 + col];
        }
        __syncthreads();
        #pragma unroll
        for (int i = 0; i < 16; i++) {
            int nn = rb + i * 4;
            float x = tile[col][nn];
            __nv_bfloat16 h = __float2bfloat16(x);
            __nv_bfloat16 l = __float2bfloat16(x - __bfloat162float(h));
            g_wt_hi[(size_t)(n0 + nn) * DIN + k0 + col] = h;
            g_wt_lo[(size_t)(n0 + nn) * DIN + k0 + col] = l;
        }
    } else if (bx < 288) {
        int idx = (bx - 32) * 256 + threadIdx.x;
        float x = Wb[idx];
        __nv_bfloat16 h = __float2bfloat16(x);
        __nv_bfloat16 l = __float2bfloat16(x - __bfloat162float(h));
        g_wb_hi[idx] = h;
        g_wb_lo[idx] = l;
    } else {
        int idx = (bx - 288) * 256 + threadIdx.x;   // 0..16383 = 2*NB
        out[idx] = b_bil[0];
    }
}

// ====== GEMM1 fused, 512 threads, double-buffered tiles + agg epilogue ======
#define RPAD    80
#define HS      258
#define BUFB    61440
#define OFF_AHI 0
#define OFF_ALO 10240
#define OFF_BHI 20480
#define OFF_BLO 40960
#define OFF_H   0
#define OFF_ADJ (128 * HS * 4)           // 132096
#define OFF_RED (OFF_ADJ + 16 * 64 * 4)  // 136192
#define SMEM_SZ (OFF_RED + 16 * 8 * 2 * 4)  // 137216

__global__ __launch_bounds__(512, 1) void gemm1_fused(
    const float* __restrict__ posx, const float* __restrict__ negx,
    const int* __restrict__ pos_src, const int* __restrict__ pos_dst,
    const float* __restrict__ pos_w,
    const int* __restrict__ neg_src, const int* __restrict__ neg_dst,
    const float* __restrict__ neg_w,
    const float* __restrict__ b_gcn, const float* __restrict__ prelu_a)
{
    extern __shared__ __align__(16) char smem[];
    float* sH   = (float*)(smem + OFF_H);
    float* sAdj = (float*)(smem + OFF_ADJ);
    float* sRed = (float*)(smem + OFF_RED);

    const int tid = threadIdx.x;
    const int wid = tid >> 5;
    const int lane = tid & 31;

    const int m0 = blockIdx.x * 128;
    const int is_pos = (m0 < NNODES);
    const int mloc = is_pos ? m0 : (m0 - NNODES);
    const int warp_m = (wid & 3) * 32;
    const int warp_n = (wid >> 2) * 64;

    const float* X = (is_pos ? posx : negx) + (size_t)mloc * DIN;
    const int*   src = is_pos ? pos_src : neg_src;
    const int*   dst = is_pos ? pos_dst : neg_dst;
    const float* ew  = is_pos ? pos_w   : neg_w;

    const uint32_t sb = smem_u32(smem);

    // ---- build 16 adjacency matrices early ----
    sAdj[tid] = 0.f;
    sAdj[tid + 512] = 0.f;
    __syncthreads();
    {
        const int eb = mloc * 8;
        int2 s2 = *(const int2*)(src + eb + tid * 2);
        int2 d2 = *(const int2*)(dst + eb + tid * 2);
        float2 w2 = *(const float2*)(ew + eb + tid * 2);
        int blk = tid >> 5;
        atomicAdd(&sAdj[blk * 64 + (d2.x & 7) * 8 + (s2.x & 7)], w2.x);
        atomicAdd(&sAdj[blk * 64 + (d2.y & 7) * 8 + (s2.y & 7)], w2.y);
    }

    const int a_lrow = tid >> 2;
    const int a_part = (tid & 3) * 8;
    const float* aptr = X + (size_t)a_lrow * DIN + a_part;
    const uint32_t a_st = (uint32_t)a_lrow * RPAD + (uint32_t)a_part * 2;

    const int b_lrow = tid >> 1;
    const int b_part = (tid & 1) * 16;
    const __nv_bfloat16* bh_ptr = g_wt_hi + (size_t)b_lrow * DIN + b_part;
    const __nv_bfloat16* bl_ptr = g_wt_lo + (size_t)b_lrow * DIN + b_part;
    const uint32_t b_st = (uint32_t)b_lrow * RPAD + (uint32_t)b_part * 2;

    const int a_r  = lane & 15;
    const int a_cg = lane >> 4;
    const int b_t  = lane >> 3;
    const int b_r  = lane & 7;
    const int b_nn = ((b_t >> 1) << 3) + b_r;
    const int b_kk = (b_t & 1) << 3;

    float acc[2][8][4];
    #pragma unroll
    for (int i = 0; i < 2; i++)
        #pragma unroll
        for (int j = 0; j < 8; j++)
            #pragma unroll
            for (int q = 0; q < 4; q++) acc[i][j][q] = 0.f;

    float4 pA0 = *(const float4*)(aptr + 0);
    float4 pA1 = *(const float4*)(aptr + 4);
    uint4 pBh0 = *(const uint4*)((const char*)bh_ptr);
    uint4 pBh1 = *(const uint4*)((const char*)bh_ptr + 16);
    uint4 pBl0 = *(const uint4*)((const char*)bl_ptr);
    uint4 pBl1 = *(const uint4*)((const char*)bl_ptr + 16);
    {
        uint32_t h[4], l[4];
        split2(pA0.x, pA0.y, h[0], l[0]);
        split2(pA0.z, pA0.w, h[1], l[1]);
        split2(pA1.x, pA1.y, h[2], l[2]);
        split2(pA1.z, pA1.w, h[3], l[3]);
        *(uint4*)(smem + OFF_AHI + a_st) = make_uint4(h[0], h[1], h[2], h[3]);
        *(uint4*)(smem + OFF_ALO + a_st) = make_uint4(l[0], l[1], l[2], l[3]);
        *(uint4*)(smem + OFF_BHI + b_st)      = pBh0;
        *(uint4*)(smem + OFF_BHI + b_st + 16) = pBh1;
        *(uint4*)(smem + OFF_BLO + b_st)      = pBl0;
        *(uint4*)(smem + OFF_BLO + b_st + 16) = pBl1;
    }
    __syncthreads();

    for (int kt = 0; kt < DIN / 32; kt++) {
        const uint32_t cb = (uint32_t)(kt & 1) * BUFB;

        if (kt < DIN / 32 - 1) {
            const float* ap = aptr + (kt + 1) * 32;
            pA0 = *(const float4*)(ap + 0);
            pA1 = *(const float4*)(ap + 4);
            const char* bh = (const char*)(bh_ptr + (kt + 1) * 32);
            const char* bl = (const char*)(bl_ptr + (kt + 1) * 32);
            pBh0 = *(const uint4*)(bh);
            pBh1 = *(const uint4*)(bh + 16);
            pBl0 = *(const uint4*)(bl);
            pBl1 = *(const uint4*)(bl + 16);
        }

        const uint32_t ahi_b = sb + cb + OFF_AHI;
        const uint32_t alo_b = sb + cb + OFF_ALO;
        const uint32_t bhi_b = sb + cb + OFF_BHI;
        const uint32_t blo_b = sb + cb + OFF_BLO;
        #pragma unroll
        for (int k16 = 0; k16 < 32; k16 += 16) {
            uint32_t ahi[2][4], alo[2][4];
            #pragma unroll
            for (int mi = 0; mi < 2; mi++) {
                const uint32_t a_off = (uint32_t)(warp_m + mi * 16 + a_r) * RPAD
                                     + (uint32_t)(k16 + a_cg * 8) * 2;
                LDSM_X4(ahi[mi][0], ahi[mi][1], ahi[mi][2], ahi[mi][3], ahi_b + a_off);
                LDSM_X4(alo[mi][0], alo[mi][1], alo[mi][2], alo[mi][3], alo_b + a_off);
            }
            #pragma unroll
            for (int g = 0; g < 4; g++) {
                const uint32_t b_off = (uint32_t)(warp_n + g * 16 + b_nn) * RPAD
                                     + (uint32_t)(k16 + b_kk) * 2;
                uint32_t bh[4], bl[4];
                LDSM_X4(bh[0], bh[1], bh[2], bh[3], bhi_b + b_off);
                LDSM_X4(bl[0], bl[1], bl[2], bl[3], blo_b + b_off);
                #pragma unroll
                for (int mi = 0; mi < 2; mi++) {
                    MMA16816(acc[mi][g * 2 + 0], ahi[mi], bh[0], bh[1]);
                    MMA16816(acc[mi][g * 2 + 1], ahi[mi], bh[2], bh[3]);
                    MMA16816(acc[mi][g * 2 + 0], alo[mi], bh[0], bh[1]);
                    MMA16816(acc[mi][g * 2 + 1], alo[mi], bh[2], bh[3]);
                    MMA16816(acc[mi][g * 2 + 0], ahi[mi], bl[0], bl[1]);
                    MMA16816(acc[mi][g * 2 + 1], ahi[mi], bl[2], bl[3]);
                }
            }
        }

        if (kt < DIN / 32 - 1) {
            const uint32_t nb = (uint32_t)((kt + 1) & 1) * BUFB;
            uint32_t h[4], l[4];
            split2(pA0.x, pA0.y, h[0], l[0]);
            split2(pA0.z, pA0.w, h[1], l[1]);
            split2(pA1.x, pA1.y, h[2], l[2]);
            split2(pA1.z, pA1.w, h[3], l[3]);
            *(uint4*)(smem + nb + OFF_AHI + a_st) = make_uint4(h[0], h[1], h[2], h[3]);
            *(uint4*)(smem + nb + OFF_ALO + a_st) = make_uint4(l[0], l[1], l[2], l[3]);
            *(uint4*)(smem + nb + OFF_BHI + b_st)      = pBh0;
            *(uint4*)(smem + nb + OFF_BHI + b_st + 16) = pBh1;
            *(uint4*)(smem + nb + OFF_BLO + b_st)      = pBl0;
            *(uint4*)(smem + nb + OFF_BLO + b_st + 16) = pBl1;
        }
        __syncthreads();
    }

    // ---- epilogue: acc -> smem h (stride HS) ----
    const int er = lane >> 2;
    const int ec = (lane & 3) * 2;
    #pragma unroll
    for (int mi = 0; mi < 2; mi++) {
        #pragma unroll
        for (int nf = 0; nf < 8; nf++) {
            int row = warp_m + mi * 16 + er;
            int col = warp_n + nf * 8 + ec;
            *(float2*)&sH[(size_t)row * HS + col] =
                make_float2(acc[mi][nf][0], acc[mi][nf][1]);
            *(float2*)&sH[(size_t)(row + 8) * HS + col] =
                make_float2(acc[mi][nf][2], acc[mi][nf][3]);
        }
    }
    __syncthreads();

    // ---- agg + PReLU + pool/anchor ----
    const int half = tid >> 8;
    const int col  = tid & 255;
    const int hw   = wid & 7;
    const float pa = prelu_a[0];
    const float bj = b_gcn[col];
    float poolv[8], anchv[8], vp[8], va[8];
    #pragma unroll
    for (int q = 0; q < 8; q++) {
        const int blk = half * 8 + q;
        float x[SS];
        #pragma unroll
        for (int s = 0; s < SS; s++) x[s] = sH[(size_t)(blk * 8 + s) * HS + col];
        float pool = 0.f, anchor = 0.f;
        #pragma unroll
        for (int r = 0; r < SS; r++) {
            float a = bj;
            #pragma unroll
            for (int s = 0; s < SS; s++)
                a = fmaf(sAdj[blk * 64 + r * 8 + s], x[s], a);
            float h = (a >= 0.f) ? a : pa * a;
            if (r < SS - 1) pool += h;
            else            anchor = h;
        }
        pool *= (1.0f / (float)(SS - 1));
        poolv[q] = pool;
        anchv[q] = anchor;
        float p2s = pool * pool, a2s = anchor * anchor;
        #pragma unroll
        for (int o = 16; o; o >>= 1) {
            p2s += __shfl_xor_sync(0xffffffffu, p2s, o);
            a2s += __shfl_xor_sync(0xffffffffu, a2s, o);
        }
        vp[q] = p2s;
        va[q] = a2s;
    }
    if (lane == 0) {
        #pragma unroll
        for (int q = 0; q < 8; q++) {
            const int blk = half * 8 + q;
            sRed[blk * 16 + hw * 2 + 0] = vp[q];
            sRed[blk * 16 + hw * 2 + 1] = va[q];
        }
    }
    __syncthreads();

    const int b0 = mloc / SS;
    #pragma unroll
    for (int q = 0; q < 8; q++) {
        const int blk = half * 8 + q;
        float sp = 0.f, sa = 0.f;
        #pragma unroll
        for (int w = 0; w < 8; w++) {
            sp += sRed[blk * 16 + w * 2 + 0];
            sa += sRed[blk * 16 + w * 2 + 1];
        }
        const float inp = 1.f / fmaxf(sqrtf(sp), 1e-12f);
        const float ina = 1.f / fmaxf(sqrtf(sa), 1e-12f);
        const size_t gi = (size_t)(b0 + blk) * DOUT + col;
        if (is_pos) {
            g_pos_pool[gi] = poolv[q] * inp;
            g_anchor[gi]   = anchv[q] * ina;
        } else {
            g_neg_pool[gi] = poolv[q] * inp;
        }
    }
}

// ====== GEMM2 via bf16 3-term mma + fused score, single wave (128 CTAs) ======
#define TS 132
#define G2_AHI 0
#define G2_ALO 10240
#define G2_BHI 20480
#define G2_BLO 30720
#define G2_SMEM (128 * TS * 4)   // 67584

__global__ __launch_bounds__(256, 1) void gemm2_mma(float* __restrict__ out)
{
    extern __shared__ __align__(16) char smem[];
    float* sT = (float*)smem;

    const int tid = threadIdx.x;
    const int wid = tid >> 5;
    const int lane = tid & 31;

    const int m0 = blockIdx.x * 128;
    const int n0 = blockIdx.y * 128;
    const int warp_m = (wid & 3) * 32;
    const int warp_n = (wid >> 2) * 64;

    const uint32_t sb = smem_u32(smem);

    const int a_lrow = tid >> 1;
    const int a_part = (tid & 1) * 16;
    const float* aptr = g_anchor + (size_t)(m0 + a_lrow) * DOUT + a_part;
    const uint32_t a_st = (uint32_t)a_lrow * RPAD + (uint32_t)a_part * 2;

    const int b_lrow = tid >> 1;
    const int b_part = (tid & 1) * 16;
    const __nv_bfloat16* bh_ptr = g_wb_hi + (size_t)(n0 + b_lrow) * DOUT + b_part;
    const __nv_bfloat16* bl_ptr = g_wb_lo + (size_t)(n0 + b_lrow) * DOUT + b_part;
    const uint32_t b_st = (uint32_t)b_lrow * RPAD + (uint32_t)b_part * 2;

    const int a_r  = lane & 15;
    const int a_cg = lane >> 4;
    const int b_t  = lane >> 3;
    const int b_r  = lane & 7;
    const int b_nn = ((b_t >> 1) << 3) + b_r;
    const int b_kk = (b_t & 1) << 3;

    float acc[2][8][4];
    #pragma unroll
    for (int i = 0; i < 2; i++)
        #pragma unroll
        for (int j = 0; j < 8; j++)
            #pragma unroll
            for (int q = 0; q < 4; q++) acc[i][j][q] = 0.f;

    for (int kt = 0; kt < DOUT / 32; kt++) {
        const int k0 = kt * 32;
        {
            const float* ap = aptr + k0;
            float4 v0 = *(const float4*)(ap + 0);
            float4 v1 = *(const float4*)(ap + 4);
            float4 v2 = *(const float4*)(ap + 8);
            float4 v3 = *(const float4*)(ap + 12);
            uint32_t h[8], l[8];
            split2(v0.x, v0.y, h[0], l[0]);
            split2(v0.z, v0.w, h[1], l[1]);
            split2(v1.x, v1.y, h[2], l[2]);
            split2(v1.z, v1.w, h[3], l[3]);
            split2(v2.x, v2.y, h[4], l[4]);
            split2(v2.z, v2.w, h[5], l[5]);
            split2(v3.x, v3.y, h[6], l[6]);
            split2(v3.z, v3.w, h[7], l[7]);
            *(uint4*)(smem + G2_AHI + a_st)      = make_uint4(h[0], h[1], h[2], h[3]);
            *(uint4*)(smem + G2_AHI + a_st + 16) = make_uint4(h[4], h[5], h[6], h[7]);
            *(uint4*)(smem + G2_ALO + a_st)      = make_uint4(l[0], l[1], l[2], l[3]);
            *(uint4*)(smem + G2_ALO + a_st + 16) = make_uint4(l[4], l[5], l[6], l[7]);
        }
        {
            const char* bh = (const char*)(bh_ptr + k0);
            const char* bl = (const char*)(bl_ptr + k0);
            uint4 h0 = *(const uint4*)(bh);
            uint4 h1 = *(const uint4*)(bh + 16);
            uint4 l0 = *(const uint4*)(bl);
            uint4 l1 = *(const uint4*)(bl + 16);
            *(uint4*)(smem + G2_BHI + b_st)      = h0;
            *(uint4*)(smem + G2_BHI + b_st + 16) = h1;
            *(uint4*)(smem + G2_BLO + b_st)      = l0;
            *(uint4*)(smem + G2_BLO + b_st + 16) = l1;
        }
        __syncthreads();

        #pragma unroll
        for (int k16 = 0; k16 < 32; k16 += 16) {
            uint32_t ahi[2][4], alo[2][4];
            #pragma unroll
            for (int mi = 0; mi < 2; mi++) {
                const uint32_t a_off = (uint32_t)(warp_m + mi * 16 + a_r) * RPAD
                                     + (uint32_t)(k16 + a_cg * 8) * 2;
                LDSM_X4(ahi[mi][0], ahi[mi][1], ahi[mi][2], ahi[mi][3], sb + G2_AHI + a_off);
                LDSM_X4(alo[mi][0], alo[mi][1], alo[mi][2], alo[mi][3], sb + G2_ALO + a_off);
            }
            #pragma unroll
            for (int g = 0; g < 4; g++) {
                const uint32_t b_off = (uint32_t)(warp_n + g * 16 + b_nn) * RPAD
                                     + (uint32_t)(k16 + b_kk) * 2;
                uint32_t bh[4], bl[4];
                LDSM_X4(bh[0], bh[1], bh[2], bh[3], sb + G2_BHI + b_off);
                LDSM_X4(bl[0], bl[1], bl[2], bl[3], sb + G2_BLO + b_off);
                #pragma unroll
                for (int mi = 0; mi < 2; mi++) {
                    MMA16816(acc[mi][g * 2 + 0], ahi[mi], bh[0], bh[1]);
                    MMA16816(acc[mi][g * 2 + 1], ahi[mi], bh[2], bh[3]);
                    MMA16816(acc[mi][g * 2 + 0], alo[mi], bh[0], bh[1]);
                    MMA16816(acc[mi][g * 2 + 1], alo[mi], bh[2], bh[3]);
                    MMA16816(acc[mi][g * 2 + 0], ahi[mi], bl[0], bl[1]);
                    MMA16816(acc[mi][g * 2 + 1], ahi[mi], bl[2], bl[3]);
                }
            }
        }
        __syncthreads();
    }

    // ---- T tile -> smem ----
    const int er = lane >> 2;
    const int ec = (lane & 3) * 2;
    #pragma unroll
    for (int mi = 0; mi < 2; mi++) {
        #pragma unroll
        for (int nf = 0; nf < 8; nf++) {
            int row = warp_m + mi * 16 + er;
            int col = warp_n + nf * 8 + ec;
            *(float2*)&sT[(size_t)row * TS + col] =
                make_float2(acc[mi][nf][0], acc[mi][nf][1]);
            *(float2*)&sT[(size_t)(row + 8) * TS + col] =
                make_float2(acc[mi][nf][2], acc[mi][nf][3]);
        }
    }
    __syncthreads();

    // ---- fused score ----
    #pragma unroll
    for (int rr = 0; rr < 16; rr++) {
        const int r = wid * 16 + rr;
        const int grow = m0 + r;
        const float* pp = g_pos_pool + (size_t)grow * DOUT + n0;
        const float* np = g_neg_pool + (size_t)grow * DOUT + n0;
        float sp = 0.f, sn = 0.f;
        #pragma unroll
        for (int q = 0; q < 4; q++) {
            float t = sT[(size_t)r * TS + lane + q * 32];
            sp = fmaf(t, pp[lane + q * 32], sp);
            sn = fmaf(t, np[lane + q * 32], sn);
        }
        #pragma unroll
        for (int o = 16; o; o >>= 1) {
            sp += __shfl_xor_sync(0xffffffffu, sp, o);
            sn += __shfl_xor_sync(0xffffffffu, sn, o);
        }
        if (lane == 0) {
            atomicAdd(&out[grow], sp);
            atomicAdd(&out[NB + grow], sn);
        }
    }
}

extern "C" void kernel_launch(void* const* d_in, const int* in_sizes, int n_in,
                              void* d_out, int out_size)
{
    const float* pos_x   = (const float*)d_in[0];
    const float* neg_x   = (const float*)d_in[1];
    const int*   pos_src = (const int*)d_in[2];
    const int*   pos_dst = (const int*)d_in[3];
    const float* pos_w   = (const float*)d_in[4];
    const int*   neg_src = (const int*)d_in[5];
    const int*   neg_dst = (const int*)d_in[6];
    const float* neg_w   = (const float*)d_in[7];
    const float* W_gcn   = (const float*)d_in[8];
    const float* b_gcn   = (const float*)d_in[9];
    const float* prelu_a = (const float*)d_in[10];
    const float* W_bil   = (const float*)d_in[11];
    const float* b_bil   = (const float*)d_in[12];
    float* out = (float*)d_out;

    (void)in_sizes; (void)n_in; (void)out_size;

    cudaFuncSetAttribute(gemm1_fused, cudaFuncAttributeMaxDynamicSharedMemorySize,
                         SMEM_SZ);
    cudaFuncSetAttribute(gemm2_mma, cudaFuncAttributeMaxDynamicSharedMemorySize,
                         G2_SMEM);

    // 0) combined prologue: coalesced weight splits + out init (one launch)
    prologue_kernel<<<352, 256>>>(W_gcn, W_bil, b_bil, out);

    // 1) fused: xw GEMM + agg + PReLU + pool + anchor + L2 norm
    gemm1_fused<<<2 * NNODES / 128, 512, SMEM_SZ>>>(
        pos_x, neg_x, pos_src, pos_dst, pos_w,
        neg_src, neg_dst, neg_w, b_gcn, prelu_a);

    // 2) T = anchor @ W_bil^T (bf16 3-term mma) + fused scores
    gemm2_mma<<<dim3(NB / 128, DOUT / 128), 256, G2_SMEM>>>(out);
}

// round 17
// speedup vs baseline: 1.4328x; 1.0098x over previous
#include <cuda_runtime.h>
#include <cuda_bf16.h>
#include <cstdint>
#include <math.h>

#define NNODES 65536   // nodes per branch (B*S)
#define NB     8192    // graph blocks
#define SS     8       // nodes per block
#define EPB    64      // edges per block
#define DIN    512
#define DOUT   256

// ---- scratch (static device globals; no allocation allowed) ----
__device__ float g_pos_pool[NB * DOUT];
__device__ float g_neg_pool[NB * DOUT];
__device__ float g_anchor[NB * DOUT];
__device__ __nv_bfloat16 g_wt_hi[DOUT * DIN];   // W_gcn^T split-hi [256][512]
__device__ __nv_bfloat16 g_wt_lo[DOUT * DIN];   // W_gcn^T split-lo
__device__ __nv_bfloat16 g_wb_hi[DOUT * DOUT];  // W_bil split-hi [256][256]
__device__ __nv_bfloat16 g_wb_lo[DOUT * DOUT];  // W_bil split-lo

// ======================= helpers =======================
__device__ __forceinline__ uint32_t smem_u32(const void* p) {
    uint32_t a;
    asm("{ .reg .u64 t; cvta.to.shared.u64 t, %1; cvt.u32.u64 %0, t; }"
        : "=r"(a) : "l"(p));
    return a;
}

#define LDSM_X4(r0, r1, r2, r3, addr) \
    asm volatile("ldmatrix.sync.aligned.m8n8.x4.shared.b16 {%0,%1,%2,%3}, [%4];" \
        : "=r"(r0), "=r"(r1), "=r"(r2), "=r"(r3) : "r"(addr))

#define MMA16816(d, a, b0, b1) \
    asm volatile("mma.sync.aligned.m16n8k16.row.col.f32.bf16.bf16.f32 " \
        "{%0,%1,%2,%3}, {%4,%5,%6,%7}, {%8,%9}, {%0,%1,%2,%3};" \
        : "+f"((d)[0]), "+f"((d)[1]), "+f"((d)[2]), "+f"((d)[3]) \
        : "r"((a)[0]), "r"((a)[1]), "r"((a)[2]), "r"((a)[3]), "r"(b0), "r"(b1))

__device__ __forceinline__ void split2(float x0, float x1, uint32_t& h, uint32_t& l) {
    __nv_bfloat16 h0 = __float2bfloat16(x0);
    __nv_bfloat16 h1 = __float2bfloat16(x1);
    __nv_bfloat16 l0 = __float2bfloat16(x0 - __bfloat162float(h0));
    __nv_bfloat16 l1 = __float2bfloat16(x1 - __bfloat162float(h1));
    __nv_bfloat162 hh = __halves2bfloat162(h0, h1);
    __nv_bfloat162 ll = __halves2bfloat162(l0, l1);
    h = *reinterpret_cast<uint32_t*>(&hh);
    l = *reinterpret_cast<uint32_t*>(&ll);
}

// ===== combined prologue (coalesced): W_gcn tile-transpose split, W_bil split, out init =====
__global__ __launch_bounds__(256) void prologue_kernel(
    const float* __restrict__ Wg, const float* __restrict__ Wb,
    const float* __restrict__ b_bil, float* __restrict__ out)
{
    const int bx = blockIdx.x;
    if (bx < 32) {
        __shared__ float tile[64][65];
        const int k0 = (bx >> 2) * 64;
        const int n0 = (bx & 3) * 64;
        const int col = threadIdx.x & 63;
        const int rb  = threadIdx.x >> 6;
        #pragma unroll
        for (int i = 0; i < 16; i++) {
            int row = rb + i * 4;
            tile[row][col] = Wg[(size_t)(k0 + row) * DOUT + n0 + col];
        }
        __syncthreads();
        #pragma unroll
        for (int i = 0; i < 16; i++) {
            int nn = rb + i * 4;
            float x = tile[col][nn];
            __nv_bfloat16 h = __float2bfloat16(x);
            __nv_bfloat16 l = __float2bfloat16(x - __bfloat162float(h));
            g_wt_hi[(size_t)(n0 + nn) * DIN + k0 + col] = h;
            g_wt_lo[(size_t)(n0 + nn) * DIN + k0 + col] = l;
        }
    } else if (bx < 288) {
        int idx = (bx - 32) * 256 + threadIdx.x;
        float x = Wb[idx];
        __nv_bfloat16 h = __float2bfloat16(x);
        __nv_bfloat16 l = __float2bfloat16(x - __bfloat162float(h));
        g_wb_hi[idx] = h;
        g_wb_lo[idx] = l;
    } else {
        int idx = (bx - 288) * 256 + threadIdx.x;
        out[idx] = b_bil[0];
    }
}

// ====== GEMM1 fused, 512 threads, double-buffered tiles + agg epilogue ======
#define RPAD    80
#define HS      258
#define BUFB    61440
#define OFF_AHI 0
#define OFF_ALO 10240
#define OFF_BHI 20480
#define OFF_BLO 40960
#define OFF_H   0
#define OFF_ADJ (128 * HS * 4)           // 132096
#define OFF_RED (OFF_ADJ + 16 * 64 * 4)  // 136192
#define SMEM_SZ (OFF_RED + 16 * 8 * 2 * 4)  // 137216

__global__ __launch_bounds__(512, 1) void gemm1_fused(
    const float* __restrict__ posx, const float* __restrict__ negx,
    const int* __restrict__ pos_src, const int* __restrict__ pos_dst,
    const float* __restrict__ pos_w,
    const int* __restrict__ neg_src, const int* __restrict__ neg_dst,
    const float* __restrict__ neg_w,
    const float* __restrict__ b_gcn, const float* __restrict__ prelu_a)
{
    extern __shared__ __align__(16) char smem[];
    float* sH   = (float*)(smem + OFF_H);
    float* sAdj = (float*)(smem + OFF_ADJ);
    float* sRed = (float*)(smem + OFF_RED);

    const int tid = threadIdx.x;
    const int wid = tid >> 5;
    const int lane = tid & 31;

    const int m0 = blockIdx.x * 128;
    const int is_pos = (m0 < NNODES);
    const int mloc = is_pos ? m0 : (m0 - NNODES);
    const int warp_m = (wid & 3) * 32;
    const int warp_n = (wid >> 2) * 64;

    const float* X = (is_pos ? posx : negx) + (size_t)mloc * DIN;
    const int*   src = is_pos ? pos_src : neg_src;
    const int*   dst = is_pos ? pos_dst : neg_dst;
    const float* ew  = is_pos ? pos_w   : neg_w;

    const uint32_t sb = smem_u32(smem);

    sAdj[tid] = 0.f;
    sAdj[tid + 512] = 0.f;
    __syncthreads();
    {
        const int eb = mloc * 8;
        int2 s2 = *(const int2*)(src + eb + tid * 2);
        int2 d2 = *(const int2*)(dst + eb + tid * 2);
        float2 w2 = *(const float2*)(ew + eb + tid * 2);
        int blk = tid >> 5;
        atomicAdd(&sAdj[blk * 64 + (d2.x & 7) * 8 + (s2.x & 7)], w2.x);
        atomicAdd(&sAdj[blk * 64 + (d2.y & 7) * 8 + (s2.y & 7)], w2.y);
    }

    const int a_lrow = tid >> 2;
    const int a_part = (tid & 3) * 8;
    const float* aptr = X + (size_t)a_lrow * DIN + a_part;
    const uint32_t a_st = (uint32_t)a_lrow * RPAD + (uint32_t)a_part * 2;

    const int b_lrow = tid >> 1;
    const int b_part = (tid & 1) * 16;
    const __nv_bfloat16* bh_ptr = g_wt_hi + (size_t)b_lrow * DIN + b_part;
    const __nv_bfloat16* bl_ptr = g_wt_lo + (size_t)b_lrow * DIN + b_part;
    const uint32_t b_st = (uint32_t)b_lrow * RPAD + (uint32_t)b_part * 2;

    const int a_r  = lane & 15;
    const int a_cg = lane >> 4;
    const int b_t  = lane >> 3;
    const int b_r  = lane & 7;
    const int b_nn = ((b_t >> 1) << 3) + b_r;
    const int b_kk = (b_t & 1) << 3;

    float acc[2][8][4];
    #pragma unroll
    for (int i = 0; i < 2; i++)
        #pragma unroll
        for (int j = 0; j < 8; j++)
            #pragma unroll
            for (int q = 0; q < 4; q++) acc[i][j][q] = 0.f;

    float4 pA0 = *(const float4*)(aptr + 0);
    float4 pA1 = *(const float4*)(aptr + 4);
    uint4 pBh0 = *(const uint4*)((const char*)bh_ptr);
    uint4 pBh1 = *(const uint4*)((const char*)bh_ptr + 16);
    uint4 pBl0 = *(const uint4*)((const char*)bl_ptr);
    uint4 pBl1 = *(const uint4*)((const char*)bl_ptr + 16);
    {
        uint32_t h[4], l[4];
        split2(pA0.x, pA0.y, h[0], l[0]);
        split2(pA0.z, pA0.w, h[1], l[1]);
        split2(pA1.x, pA1.y, h[2], l[2]);
        split2(pA1.z, pA1.w, h[3], l[3]);
        *(uint4*)(smem + OFF_AHI + a_st) = make_uint4(h[0], h[1], h[2], h[3]);
        *(uint4*)(smem + OFF_ALO + a_st) = make_uint4(l[0], l[1], l[2], l[3]);
        *(uint4*)(smem + OFF_BHI + b_st)      = pBh0;
        *(uint4*)(smem + OFF_BHI + b_st + 16) = pBh1;
        *(uint4*)(smem + OFF_BLO + b_st)      = pBl0;
        *(uint4*)(smem + OFF_BLO + b_st + 16) = pBl1;
    }
    __syncthreads();

    for (int kt = 0; kt < DIN / 32; kt++) {
        const uint32_t cb = (uint32_t)(kt & 1) * BUFB;

        if (kt < DIN / 32 - 1) {
            const float* ap = aptr + (kt + 1) * 32;
            pA0 = *(const float4*)(ap + 0);
            pA1 = *(const float4*)(ap + 4);
            const char* bh = (const char*)(bh_ptr + (kt + 1) * 32);
            const char* bl = (const char*)(bl_ptr + (kt + 1) * 32);
            pBh0 = *(const uint4*)(bh);
            pBh1 = *(const uint4*)(bh + 16);
            pBl0 = *(const uint4*)(bl);
            pBl1 = *(const uint4*)(bl + 16);
        }

        const uint32_t ahi_b = sb + cb + OFF_AHI;
        const uint32_t alo_b = sb + cb + OFF_ALO;
        const uint32_t bhi_b = sb + cb + OFF_BHI;
        const uint32_t blo_b = sb + cb + OFF_BLO;
        #pragma unroll
        for (int k16 = 0; k16 < 32; k16 += 16) {
            uint32_t ahi[2][4], alo[2][4];
            #pragma unroll
            for (int mi = 0; mi < 2; mi++) {
                const uint32_t a_off = (uint32_t)(warp_m + mi * 16 + a_r) * RPAD
                                     + (uint32_t)(k16 + a_cg * 8) * 2;
                LDSM_X4(ahi[mi][0], ahi[mi][1], ahi[mi][2], ahi[mi][3], ahi_b + a_off);
                LDSM_X4(alo[mi][0], alo[mi][1], alo[mi][2], alo[mi][3], alo_b + a_off);
            }
            #pragma unroll
            for (int g = 0; g < 4; g++) {
                const uint32_t b_off = (uint32_t)(warp_n + g * 16 + b_nn) * RPAD
                                     + (uint32_t)(k16 + b_kk) * 2;
                uint32_t bh[4], bl[4];
                LDSM_X4(bh[0], bh[1], bh[2], bh[3], bhi_b + b_off);
                LDSM_X4(bl[0], bl[1], bl[2], bl[3], blo_b + b_off);
                #pragma unroll
                for (int mi = 0; mi < 2; mi++) {
                    MMA16816(acc[mi][g * 2 + 0], ahi[mi], bh[0], bh[1]);
                    MMA16816(acc[mi][g * 2 + 1], ahi[mi], bh[2], bh[3]);
                    MMA16816(acc[mi][g * 2 + 0], alo[mi], bh[0], bh[1]);
                    MMA16816(acc[mi][g * 2 + 1], alo[mi], bh[2], bh[3]);
                    MMA16816(acc[mi][g * 2 + 0], ahi[mi], bl[0], bl[1]);
                    MMA16816(acc[mi][g * 2 + 1], ahi[mi], bl[2], bl[3]);
                }
            }
        }

        if (kt < DIN / 32 - 1) {
            const uint32_t nb = (uint32_t)((kt + 1) & 1) * BUFB;
            uint32_t h[4], l[4];
            split2(pA0.x, pA0.y, h[0], l[0]);
            split2(pA0.z, pA0.w, h[1], l[1]);
            split2(pA1.x, pA1.y, h[2], l[2]);
            split2(pA1.z, pA1.w, h[3], l[3]);
            *(uint4*)(smem + nb + OFF_AHI + a_st) = make_uint4(h[0], h[1], h[2], h[3]);
            *(uint4*)(smem + nb + OFF_ALO + a_st) = make_uint4(l[0], l[1], l[2], l[3]);
            *(uint4*)(smem + nb + OFF_BHI + b_st)      = pBh0;
            *(uint4*)(smem + nb + OFF_BHI + b_st + 16) = pBh1;
            *(uint4*)(smem + nb + OFF_BLO + b_st)      = pBl0;
            *(uint4*)(smem + nb + OFF_BLO + b_st + 16) = pBl1;
        }
        __syncthreads();
    }

    // ---- epilogue: acc -> smem h (stride HS) ----
    const int er = lane >> 2;
    const int ec = (lane & 3) * 2;
    #pragma unroll
    for (int mi = 0; mi < 2; mi++) {
        #pragma unroll
        for (int nf = 0; nf < 8; nf++) {
            int row = warp_m + mi * 16 + er;
            int col = warp_n + nf * 8 + ec;
            *(float2*)&sH[(size_t)row * HS + col] =
                make_float2(acc[mi][nf][0], acc[mi][nf][1]);
            *(float2*)&sH[(size_t)(row + 8) * HS + col] =
                make_float2(acc[mi][nf][2], acc[mi][nf][3]);
        }
    }
    __syncthreads();

    // ---- agg + PReLU + pool/anchor ----
    const int half = tid >> 8;
    const int col  = tid & 255;
    const int hw   = wid & 7;
    const float pa = prelu_a[0];
    const float bj = b_gcn[col];
    float poolv[8], anchv[8], vp[8], va[8];
    #pragma unroll
    for (int q = 0; q < 8; q++) {
        const int blk = half * 8 + q;
        float x[SS];
        #pragma unroll
        for (int s = 0; s < SS; s++) x[s] = sH[(size_t)(blk * 8 + s) * HS + col];
        float pool = 0.f, anchor = 0.f;
        #pragma unroll
        for (int r = 0; r < SS; r++) {
            float a = bj;
            #pragma unroll
            for (int s = 0; s < SS; s++)
                a = fmaf(sAdj[blk * 64 + r * 8 + s], x[s], a);
            float h = (a >= 0.f) ? a : pa * a;
            if (r < SS - 1) pool += h;
            else            anchor = h;
        }
        pool *= (1.0f / (float)(SS - 1));
        poolv[q] = pool;
        anchv[q] = anchor;
        float p2s = pool * pool, a2s = anchor * anchor;
        #pragma unroll
        for (int o = 16; o; o >>= 1) {
            p2s += __shfl_xor_sync(0xffffffffu, p2s, o);
            a2s += __shfl_xor_sync(0xffffffffu, a2s, o);
        }
        vp[q] = p2s;
        va[q] = a2s;
    }
    if (lane == 0) {
        #pragma unroll
        for (int q = 0; q < 8; q++) {
            const int blk = half * 8 + q;
            sRed[blk * 16 + hw * 2 + 0] = vp[q];
            sRed[blk * 16 + hw * 2 + 1] = va[q];
        }
    }
    __syncthreads();

    const int b0 = mloc / SS;
    #pragma unroll
    for (int q = 0; q < 8; q++) {
        const int blk = half * 8 + q;
        float sp = 0.f, sa = 0.f;
        #pragma unroll
        for (int w = 0; w < 8; w++) {
            sp += sRed[blk * 16 + w * 2 + 0];
            sa += sRed[blk * 16 + w * 2 + 1];
        }
        const float inp = 1.f / fmaxf(sqrtf(sp), 1e-12f);
        const float ina = 1.f / fmaxf(sqrtf(sa), 1e-12f);
        const size_t gi = (size_t)(b0 + blk) * DOUT + col;
        if (is_pos) {
            g_pos_pool[gi] = poolv[q] * inp;
            g_anchor[gi]   = anchv[q] * ina;
        } else {
            g_neg_pool[gi] = poolv[q] * inp;
        }
    }
}

// ====== GEMM2 via bf16 3-term mma + fused score, double-buffered ======
// T-tile = anchor[128 rows] @ W_bil^T (n-half 128), K=256, 8 kt chunks.
#define TS 132
#define G2_BUFB 40960
#define G2_AHI 0
#define G2_ALO 10240
#define G2_BHI 20480
#define G2_BLO 30720
#define G2_SMEM (2 * G2_BUFB)   // 81920 > 128*TS*4=67584 (sT unions buffers)

__global__ __launch_bounds__(256, 1) void gemm2_mma(float* __restrict__ out)
{
    extern __shared__ __align__(16) char smem[];
    float* sT = (float*)smem;

    const int tid = threadIdx.x;
    const int wid = tid >> 5;
    const int lane = tid & 31;

    const int m0 = blockIdx.x * 128;
    const int n0 = blockIdx.y * 128;
    const int warp_m = (wid & 3) * 32;
    const int warp_n = (wid >> 2) * 64;

    const uint32_t sb = smem_u32(smem);

    const int a_lrow = tid >> 1;
    const int a_part = (tid & 1) * 16;
    const float* aptr = g_anchor + (size_t)(m0 + a_lrow) * DOUT + a_part;
    const uint32_t a_st = (uint32_t)a_lrow * RPAD + (uint32_t)a_part * 2;

    const int b_lrow = tid >> 1;
    const int b_part = (tid & 1) * 16;
    const __nv_bfloat16* bh_ptr = g_wb_hi + (size_t)(n0 + b_lrow) * DOUT + b_part;
    const __nv_bfloat16* bl_ptr = g_wb_lo + (size_t)(n0 + b_lrow) * DOUT + b_part;
    const uint32_t b_st = (uint32_t)b_lrow * RPAD + (uint32_t)b_part * 2;

    const int a_r  = lane & 15;
    const int a_cg = lane >> 4;
    const int b_t  = lane >> 3;
    const int b_r  = lane & 7;
    const int b_nn = ((b_t >> 1) << 3) + b_r;
    const int b_kk = (b_t & 1) << 3;

    float acc[2][8][4];
    #pragma unroll
    for (int i = 0; i < 2; i++)
        #pragma unroll
        for (int j = 0; j < 8; j++)
            #pragma unroll
            for (int q = 0; q < 4; q++) acc[i][j][q] = 0.f;

    // ---- prologue: chunk 0 -> regs -> buf0 ----
    float4 pA0 = *(const float4*)(aptr + 0);
    float4 pA1 = *(const float4*)(aptr + 4);
    float4 pA2 = *(const float4*)(aptr + 8);
    float4 pA3 = *(const float4*)(aptr + 12);
    uint4 pBh0 = *(const uint4*)((const char*)bh_ptr);
    uint4 pBh1 = *(const uint4*)((const char*)bh_ptr + 16);
    uint4 pBl0 = *(const uint4*)((const char*)bl_ptr);
    uint4 pBl1 = *(const uint4*)((const char*)bl_ptr + 16);
    {
        uint32_t h[8], l[8];
        split2(pA0.x, pA0.y, h[0], l[0]);
        split2(pA0.z, pA0.w, h[1], l[1]);
        split2(pA1.x, pA1.y, h[2], l[2]);
        split2(pA1.z, pA1.w, h[3], l[3]);
        split2(pA2.x, pA2.y, h[4], l[4]);
        split2(pA2.z, pA2.w, h[5], l[5]);
        split2(pA3.x, pA3.y, h[6], l[6]);
        split2(pA3.z, pA3.w, h[7], l[7]);
        *(uint4*)(smem + G2_AHI + a_st)      = make_uint4(h[0], h[1], h[2], h[3]);
        *(uint4*)(smem + G2_AHI + a_st + 16) = make_uint4(h[4], h[5], h[6], h[7]);
        *(uint4*)(smem + G2_ALO + a_st)      = make_uint4(l[0], l[1], l[2], l[3]);
        *(uint4*)(smem + G2_ALO + a_st + 16) = make_uint4(l[4], l[5], l[6], l[7]);
        *(uint4*)(smem + G2_BHI + b_st)      = pBh0;
        *(uint4*)(smem + G2_BHI + b_st + 16) = pBh1;
        *(uint4*)(smem + G2_BLO + b_st)      = pBl0;
        *(uint4*)(smem + G2_BLO + b_st + 16) = pBl1;
    }
    __syncthreads();

    for (int kt = 0; kt < DOUT / 32; kt++) {
        const uint32_t cb = (uint32_t)(kt & 1) * G2_BUFB;

        // ---- issue next chunk's LDGs ----
        if (kt < DOUT / 32 - 1) {
            const float* ap = aptr + (kt + 1) * 32;
            pA0 = *(const float4*)(ap + 0);
            pA1 = *(const float4*)(ap + 4);
            pA2 = *(const float4*)(ap + 8);
            pA3 = *(const float4*)(ap + 12);
            const char* bh = (const char*)(bh_ptr + (kt + 1) * 32);
            const char* bl = (const char*)(bl_ptr + (kt + 1) * 32);
            pBh0 = *(const uint4*)(bh);
            pBh1 = *(const uint4*)(bh + 16);
            pBl0 = *(const uint4*)(bl);
            pBl1 = *(const uint4*)(bl + 16);
        }

        // ---- compute on buffer cb ----
        #pragma unroll
        for (int k16 = 0; k16 < 32; k16 += 16) {
            uint32_t ahi[2][4], alo[2][4];
            #pragma unroll
            for (int mi = 0; mi < 2; mi++) {
                const uint32_t a_off = (uint32_t)(warp_m + mi * 16 + a_r) * RPAD
                                     + (uint32_t)(k16 + a_cg * 8) * 2;
                LDSM_X4(ahi[mi][0], ahi[mi][1], ahi[mi][2], ahi[mi][3], sb + cb + G2_AHI + a_off);
                LDSM_X4(alo[mi][0], alo[mi][1], alo[mi][2], alo[mi][3], sb + cb + G2_ALO + a_off);
            }
            #pragma unroll
            for (int g = 0; g < 4; g++) {
                const uint32_t b_off = (uint32_t)(warp_n + g * 16 + b_nn) * RPAD
                                     + (uint32_t)(k16 + b_kk) * 2;
                uint32_t bh[4], bl[4];
                LDSM_X4(bh[0], bh[1], bh[2], bh[3], sb + cb + G2_BHI + b_off);
                LDSM_X4(bl[0], bl[1], bl[2], bl[3], sb + cb + G2_BLO + b_off);
                #pragma unroll
                for (int mi = 0; mi < 2; mi++) {
                    MMA16816(acc[mi][g * 2 + 0], ahi[mi], bh[0], bh[1]);
                    MMA16816(acc[mi][g * 2 + 1], ahi[mi], bh[2], bh[3]);
                    MMA16816(acc[mi][g * 2 + 0], alo[mi], bh[0], bh[1]);
                    MMA16816(acc[mi][g * 2 + 1], alo[mi], bh[2], bh[3]);
                    MMA16816(acc[mi][g * 2 + 0], ahi[mi], bl[0], bl[1]);
                    MMA16816(acc[mi][g * 2 + 1], ahi[mi], bl[2], bl[3]);
                }
            }
        }

        // ---- store next chunk into alternate buffer ----
        if (kt < DOUT / 32 - 1) {
            const uint32_t nb = (uint32_t)((kt + 1) & 1) * G2_BUFB;
            uint32_t h[8], l[8];
            split2(pA0.x, pA0.y, h[0], l[0]);
            split2(pA0.z, pA0.w, h[1], l[1]);
            split2(pA1.x, pA1.y, h[2], l[2]);
            split2(pA1.z, pA1.w, h[3], l[3]);
            split2(pA2.x, pA2.y, h[4], l[4]);
            split2(pA2.z, pA2.w, h[5], l[5]);
            split2(pA3.x, pA3.y, h[6], l[6]);
            split2(pA3.z, pA3.w, h[7], l[7]);
            *(uint4*)(smem + nb + G2_AHI + a_st)      = make_uint4(h[0], h[1], h[2], h[3]);
            *(uint4*)(smem + nb + G2_AHI + a_st + 16) = make_uint4(h[4], h[5], h[6], h[7]);
            *(uint4*)(smem + nb + G2_ALO + a_st)      = make_uint4(l[0], l[1], l[2], l[3]);
            *(uint4*)(smem + nb + G2_ALO + a_st + 16) = make_uint4(l[4], l[5], l[6], l[7]);
            *(uint4*)(smem + nb + G2_BHI + b_st)      = pBh0;
            *(uint4*)(smem + nb + G2_BHI + b_st + 16) = pBh1;
            *(uint4*)(smem + nb + G2_BLO + b_st)      = pBl0;
            *(uint4*)(smem + nb + G2_BLO + b_st + 16) = pBl1;
        }
        __syncthreads();
    }

    // ---- T tile -> smem ----
    const int er = lane >> 2;
    const int ec = (lane & 3) * 2;
    #pragma unroll
    for (int mi = 0; mi < 2; mi++) {
        #pragma unroll
        for (int nf = 0; nf < 8; nf++) {
            int row = warp_m + mi * 16 + er;
            int col = warp_n + nf * 8 + ec;
            *(float2*)&sT[(size_t)row * TS + col] =
                make_float2(acc[mi][nf][0], acc[mi][nf][1]);
            *(float2*)&sT[(size_t)(row + 8) * TS + col] =
                make_float2(acc[mi][nf][2], acc[mi][nf][3]);
        }
    }
    __syncthreads();

    // ---- fused score ----
    #pragma unroll
    for (int rr = 0; rr < 16; rr++) {
        const int r = wid * 16 + rr;
        const int grow = m0 + r;
        const float* pp = g_pos_pool + (size_t)grow * DOUT + n0;
        const float* np = g_neg_pool + (size_t)grow * DOUT + n0;
        float sp = 0.f, sn = 0.f;
        #pragma unroll
        for (int q = 0; q < 4; q++) {
            float t = sT[(size_t)r * TS + lane + q * 32];
            sp = fmaf(t, pp[lane + q * 32], sp);
            sn = fmaf(t, np[lane + q * 32], sn);
        }
        #pragma unroll
        for (int o = 16; o; o >>= 1) {
            sp += __shfl_xor_sync(0xffffffffu, sp, o);
            sn += __shfl_xor_sync(0xffffffffu, sn, o);
        }
        if (lane == 0) {
            atomicAdd(&out[grow], sp);
            atomicAdd(&out[NB + grow], sn);
        }
    }
}

extern "C" void kernel_launch(void* const* d_in, const int* in_sizes, int n_in,
                              void* d_out, int out_size)
{
    const float* pos_x   = (const float*)d_in[0];
    const float* neg_x   = (const float*)d_in[1];
    const int*   pos_src = (const int*)d_in[2];
    const int*   pos_dst = (const int*)d_in[3];
    const float* pos_w   = (const float*)d_in[4];
    const int*   neg_src = (const int*)d_in[5];
    const int*   neg_dst = (const int*)d_in[6];
    const float* neg_w   = (const float*)d_in[7];
    const float* W_gcn   = (const float*)d_in[8];
    const float* b_gcn   = (const float*)d_in[9];
    const float* prelu_a = (const float*)d_in[10];
    const float* W_bil   = (const float*)d_in[11];
    const float* b_bil   = (const float*)d_in[12];
    float* out = (float*)d_out;

    (void)in_sizes; (void)n_in; (void)out_size;

    cudaFuncSetAttribute(gemm1_fused, cudaFuncAttributeMaxDynamicSharedMemorySize,
                         SMEM_SZ);
    cudaFuncSetAttribute(gemm2_mma, cudaFuncAttributeMaxDynamicSharedMemorySize,
                         G2_SMEM);

    // 0) combined prologue: coalesced weight splits + out init (one launch)
    prologue_kernel<<<352, 256>>>(W_gcn, W_bil, b_bil, out);

    // 1) fused: xw GEMM + agg + PReLU + pool + anchor + L2 norm
    gemm1_fused<<<2 * NNODES / 128, 512, SMEM_SZ>>>(
        pos_x, neg_x, pos_src, pos_dst, pos_w,
        neg_src, neg_dst, neg_w, b_gcn, prelu_a);

    // 2) T = anchor @ W_bil^T (bf16 3-term mma, double-buffered) + fused scores
    gemm2_mma<<<dim3(NB / 128, DOUT / 128), 256, G2_SMEM>>>(out);
}